// round 12
// baseline (speedup 1.0000x reference)
#include <cuda_runtime.h>
#include <cuda_bf16.h>
#include <math.h>
#include <cstdint>

// Problem constants
#define BB 4
#define SS 2048
#define DD 1024
#define HH 16
#define DK 64
#define DFF 4096
#define NT (BB * SS)   // 8192 tokens
#define EPS 1e-5f
#define QSTR (3 * DD)  // row stride of fused qkv buffer

// Does this compilation pass have sm_103a-specific (tcgen05) features?
#if !defined(__CUDA_ARCH__) || defined(__CUDA_ARCH_FEAT_SM103_ALL) || \
    defined(__CUDA_ARCH_FEAT_SM100_ALL) || defined(__CUDA_ARCH_SPECIFIC__)
#define HAS_TCGEN05 1
#else
#define HAS_TCGEN05 0
#endif

// ---------------- scratch (device globals; no allocs allowed) ----------------
__device__ float g_h[(size_t)NT * DD];
__device__ float g_qkv[(size_t)NT * 3 * DD];   // fused q|k|v, row stride 3072
__device__ float g_attn[(size_t)NT * DD];
__device__ float g_x1[(size_t)NT * DD];
__device__ float g_ffn[(size_t)NT * DFF];
__device__ float g_vT[(size_t)BB * HH * DK * SS];   // [b,h,dk,s]
// transposed weights [N, K] (tf32-rounded); wqkvT = concat(wqT, wkT, wvT)
__device__ float g_wqkvT[(size_t)3 * DD * DD];
__device__ float g_woT[(size_t)DD * DD];
__device__ float g_w1T[(size_t)DFF * DD];
__device__ float g_w2T[(size_t)DD * DFF];

// ---------------- PTX helpers --------------------------------------------------
__device__ __forceinline__ uint32_t smem_u32(const void* p) {
    uint32_t a;
    asm("{ .reg .u64 t; cvta.to.shared.u64 t, %1; cvt.u32.u64 %0, t; }"
        : "=r"(a) : "l"(p));
    return a;
}
__device__ __forceinline__ uint32_t elect_one() {
    uint32_t p;
    asm volatile("{ .reg .pred p; elect.sync _|p, 0xFFFFFFFF; selp.b32 %0,1,0,p; }"
                 : "=r"(p));
    return p;
}
__device__ __forceinline__ float to_tf32(float x) {
    uint32_t u;
    asm("cvt.rna.tf32.f32 %0, %1;" : "=r"(u) : "f"(x));
    return __uint_as_float(u);
}
__device__ __forceinline__ uint32_t ctarank() {
    uint32_t r;
    asm("mov.u32 %0, %%cluster_ctarank;" : "=r"(r));
    return r;
}
#define MBAR_INIT(a, c) \
    asm volatile("mbarrier.init.shared.b64 [%0], %1;" :: "r"((uint32_t)(a)), "r"((uint32_t)(c)) : "memory")
#define MBAR_WAIT(a, par) do {                                                   \
    uint32_t _m = (uint32_t)(a); uint32_t _p = (uint32_t)(par); uint32_t _d;     \
    asm volatile("{ .reg .pred p; mbarrier.try_wait.parity.acquire.cta.shared::cta.b64 p, [%1], %2;" \
                 " selp.b32 %0,1,0,p; }" : "=r"(_d) : "r"(_m), "r"(_p) : "memory"); \
    if (!_d) {                                                                   \
        asm volatile("{ .reg .pred P1; WL_%=: mbarrier.try_wait.parity.acquire.cta.shared::cta.b64 P1, [%0], %1, 0x989680;" \
                     " @P1 bra.uni WD_%=; bra.uni WL_%=; WD_%=: }"               \
                     :: "r"(_m), "r"(_p) : "memory");                            \
    } } while (0)
// arrive on rank-0 CTA's mbarrier at the same smem offset (cluster scope)
#define MBAR_ARRIVE_RANK0(addr) \
    asm volatile("{ .reg .b32 ra; mapa.shared::cluster.u32 ra, %0, 0;" \
                 " mbarrier.arrive.shared::cluster.b64 _, [ra]; }" \
                 :: "r"((uint32_t)(addr)) : "memory")
#define CLUSTER_SYNC() do { \
    asm volatile("barrier.cluster.arrive.aligned;" ::: "memory"); \
    asm volatile("barrier.cluster.wait.aligned;" ::: "memory"); } while (0)
#define CP16(dst, src) \
    asm volatile("cp.async.cg.shared.global [%0], [%1], 16;" \
                 :: "r"((uint32_t)(dst)), "l"(src) : "memory")
#define CP_COMMIT() asm volatile("cp.async.commit_group;" ::: "memory")
#define CP_WAIT1()  asm volatile("cp.async.wait_group 1;" ::: "memory")
#define CP_WAIT0()  asm volatile("cp.async.wait_group 0;" ::: "memory")
#define FENCE_ASYNC() asm volatile("fence.proxy.async;" ::: "memory")

#if HAS_TCGEN05
#define TC_ALLOC(smem_addr, n) \
    asm volatile("tcgen05.alloc.cta_group::1.sync.aligned.shared::cta.b32 [%0], %1;" \
                 :: "r"((uint32_t)(smem_addr)), "r"((uint32_t)(n)) : "memory")
#define TC_DEALLOC(tmem, n) \
    asm volatile("tcgen05.dealloc.cta_group::1.sync.aligned.b32 %0, %1;" \
                 :: "r"(tmem), "r"((uint32_t)(n)))
#define TC_RELINQ() \
    asm volatile("tcgen05.relinquish_alloc_permit.cta_group::1.sync.aligned;")
#define TC_ALLOC_CG2(smem_addr, n) \
    asm volatile("tcgen05.alloc.cta_group::2.sync.aligned.shared::cta.b32 [%0], %1;" \
                 :: "r"((uint32_t)(smem_addr)), "r"((uint32_t)(n)) : "memory")
#define TC_DEALLOC_CG2(tmem, n) \
    asm volatile("tcgen05.dealloc.cta_group::2.sync.aligned.b32 %0, %1;" \
                 :: "r"(tmem), "r"((uint32_t)(n)))
#define TC_RELINQ_CG2() \
    asm volatile("tcgen05.relinquish_alloc_permit.cta_group::2.sync.aligned;")
#define TC_COMMIT(mbar) \
    asm volatile("tcgen05.commit.cta_group::1.mbarrier::arrive::one.shared::cluster.b64 [%0];" \
                 :: "r"((uint32_t)(mbar)) : "memory")
#define TC_COMMIT_MC_CG2(mbar, mask) \
    asm volatile("tcgen05.commit.cta_group::2.mbarrier::arrive::one.shared::cluster.multicast::cluster.b64 [%0], %1;" \
                 :: "r"((uint32_t)(mbar)), "h"((uint16_t)(mask)) : "memory")
#define TC_WAIT_LD() asm volatile("tcgen05.wait::ld.sync.aligned;" ::: "memory")
#define TC_FENCE_BEFORE() asm volatile("tcgen05.fence::before_thread_sync;" ::: "memory")
#define TC_FENCE_AFTER()  asm volatile("tcgen05.fence::after_thread_sync;" ::: "memory")
#define TC_LD_X32(r, tmem)                                                        \
    asm volatile("tcgen05.ld.sync.aligned.32x32b.x32.b32 "                        \
        "{%0,%1,%2,%3,%4,%5,%6,%7,%8,%9,%10,%11,%12,%13,%14,%15,"                 \
        "%16,%17,%18,%19,%20,%21,%22,%23,%24,%25,%26,%27,%28,%29,%30,%31}, [%32];"\
        : "=r"((r)[0]),"=r"((r)[1]),"=r"((r)[2]),"=r"((r)[3]),                    \
          "=r"((r)[4]),"=r"((r)[5]),"=r"((r)[6]),"=r"((r)[7]),                    \
          "=r"((r)[8]),"=r"((r)[9]),"=r"((r)[10]),"=r"((r)[11]),                  \
          "=r"((r)[12]),"=r"((r)[13]),"=r"((r)[14]),"=r"((r)[15]),                \
          "=r"((r)[16]),"=r"((r)[17]),"=r"((r)[18]),"=r"((r)[19]),                \
          "=r"((r)[20]),"=r"((r)[21]),"=r"((r)[22]),"=r"((r)[23]),                \
          "=r"((r)[24]),"=r"((r)[25]),"=r"((r)[26]),"=r"((r)[27]),                \
          "=r"((r)[28]),"=r"((r)[29]),"=r"((r)[30]),"=r"((r)[31])                 \
        : "r"(tmem))

static constexpr uint64_t DESC_SW128 =
    (uint64_t(2) << 61) | (uint64_t(1) << 46) | (uint64_t(64) << 32) | (uint64_t(1) << 16);
__device__ __forceinline__ uint64_t make_desc(uint32_t addr) {
    return DESC_SW128 | ((uint64_t)(addr >> 4) & 0x3FFF);
}
// tf32 idesc: c=F32(1<<4), a=TF32(2<<7), b=TF32(2<<10), N<<17/8, M<<24/16
#define IDESC_TF32_N128      0x8200910u   // M=128, N=128 (cg1, attention)
#define IDESC_TF32_N64       0x8100910u   // M=128, N=64  (cg1, attention)
#define IDESC_TF32_M256_N256 0x10400910u  // M=256, N=256 (cg2, GEMM)
__device__ __forceinline__ void mma_tf32_ss(uint32_t d, uint64_t ad, uint64_t bd,
                                            uint32_t idesc, uint32_t en) {
    uint32_t zero = 0;
    asm volatile("{ .reg .pred p; setp.ne.u32 p, %6, 0;"
                 " tcgen05.mma.cta_group::1.kind::tf32 [%0], %1, %2, %3, "
                 "{%4, %4, %4, %4}, p; }"
                 :: "r"(d), "l"(ad), "l"(bd), "r"(idesc),
                    "r"(zero), "r"(zero), "r"(en) : "memory");
}
__device__ __forceinline__ void mma_tf32_ss_cg2(uint32_t d, uint64_t ad, uint64_t bd,
                                                uint32_t idesc, uint32_t en) {
    uint32_t zero = 0;
    asm volatile("{ .reg .pred p; setp.ne.u32 p, %6, 0;"
                 " tcgen05.mma.cta_group::2.kind::tf32 [%0], %1, %2, %3, "
                 "{%4, %4, %4, %4, %4, %4, %4, %4}, p; }"
                 :: "r"(d), "l"(ad), "l"(bd), "r"(idesc),
                    "r"(zero), "r"(zero), "r"(en) : "memory");
}
#endif  // HAS_TCGEN05

// ---------------- weight transpose: out[C][R] = tf32(in[R][C]) ----------------
__global__ __launch_bounds__(256) void transpose_kernel(const float* __restrict__ in,
                                                        float* __restrict__ out,
                                                        int R, int C) {
    __shared__ float t[32][33];
    int tx = threadIdx.x & 31, ty = threadIdx.x >> 5;  // 32 x 8
    int c0 = blockIdx.x * 32, r0 = blockIdx.y * 32;
#pragma unroll
    for (int i = 0; i < 4; i++)
        t[ty + 8 * i][tx] = in[(size_t)(r0 + ty + 8 * i) * C + c0 + tx];
    __syncthreads();
#pragma unroll
    for (int i = 0; i < 4; i++)
        out[(size_t)(c0 + ty + 8 * i) * R + r0 + tx] = to_tf32(t[tx][ty + 8 * i]);
}

// ---------------- v transpose (from fused qkv) -> vT[b,h,dk,s] ----------------
__global__ __launch_bounds__(256) void vt_kernel(const float* __restrict__ vsec,
                                                 float* __restrict__ vT) {
    __shared__ float t[32][33];
    int tx = threadIdx.x & 31, ty = threadIdx.x >> 5;
    int bh = blockIdx.z;
    int b = bh >> 4, h = bh & 15;
    int s0 = blockIdx.x * 32, d0 = blockIdx.y * 32;
#pragma unroll
    for (int i = 0; i < 4; i++)
        t[ty + 8 * i][tx] =
            vsec[(size_t)(b * SS + s0 + ty + 8 * i) * QSTR + h * 64 + d0 + tx];
    __syncthreads();
#pragma unroll
    for (int i = 0; i < 4; i++)
        vT[((size_t)bh * DK + d0 + ty + 8 * i) * SS + s0 + tx] = t[tx][ty + 8 * i];
}

// ---------------- LayerNorm: 1 warp per row, no block syncs -------------------
__global__ __launch_bounds__(256) void ln_kernel(const float* __restrict__ x,
                                                 const float* __restrict__ g,
                                                 const float* __restrict__ b,
                                                 float* __restrict__ out) {
    int w = threadIdx.x >> 5, lane = threadIdx.x & 31;
    int row = blockIdx.x * 8 + w;
    const float4* xr = reinterpret_cast<const float4*>(x + (size_t)row * DD);
    float4 v[8];
    float s = 0.f;
#pragma unroll
    for (int i = 0; i < 8; i++) {
        v[i] = xr[lane + 32 * i];
        s += v[i].x + v[i].y + v[i].z + v[i].w;
    }
#pragma unroll
    for (int o = 16; o > 0; o >>= 1) s += __shfl_xor_sync(~0u, s, o);
    float mu = s * (1.f / DD);
    float s2 = 0.f;
#pragma unroll
    for (int i = 0; i < 8; i++) {
        float dx = v[i].x - mu, dy = v[i].y - mu, dz = v[i].z - mu, dw = v[i].w - mu;
        s2 += dx * dx + dy * dy + dz * dz + dw * dw;
    }
#pragma unroll
    for (int o = 16; o > 0; o >>= 1) s2 += __shfl_xor_sync(~0u, s2, o);
    float rstd = rsqrtf(s2 * (1.f / DD) + EPS);
    const float4* gp = reinterpret_cast<const float4*>(g);
    const float4* bp = reinterpret_cast<const float4*>(b);
    float4* op = reinterpret_cast<float4*>(out + (size_t)row * DD);
#pragma unroll
    for (int i = 0; i < 8; i++) {
        float4 gg = gp[lane + 32 * i], bb = bp[lane + 32 * i], o;
        o.x = to_tf32((v[i].x - mu) * rstd * gg.x + bb.x);
        o.y = to_tf32((v[i].y - mu) * rstd * gg.y + bb.y);
        o.z = to_tf32((v[i].z - mu) * rstd * gg.z + bb.z);
        o.w = to_tf32((v[i].w - mu) * rstd * gg.w + bb.w);
        op[lane + 32 * i] = o;
    }
}

// ---------------- GEMM (cg2): C[M,N] = A[M,K] @ BT[N,K]^T ---------------------
// Cluster (2,1,1) along x, matching the in-tree cg2 examples: CTA pair
// {2m, 2m+1} computes a 256x256 tile. blockIdx.x = 128-row M tile (rank = x&1),
// blockIdx.y = 256-wide N tile. Each CTA loads its 128 A-rows + its half of B.
// smem: tmem ptr @0, full mbars @8/16 (count 2, rank0's used), done @24/32,
// stages @1024 (2 x 32KB: A 16KB + B 16KB).
#define TN 256
#define NST 2
#define STAGE 32768
#define GT_SMEM (1024 + NST * STAGE)   // 66560

template <bool BIAS, bool RELU, bool RES, bool TF32OUT, bool QKVSCALE>
__global__ __launch_bounds__(256) __cluster_dims__(2, 1, 1)
void gemm_tc(const float* __restrict__ A, const float* __restrict__ BT,
             const float* __restrict__ bias, const float* __restrict__ res,
             float* __restrict__ C, int N, int K) {
#if HAS_TCGEN05
    extern __shared__ char smem[];
    uint32_t sb = smem_u32(smem);
    int tid = threadIdx.x;
    int wid = tid >> 5, lid = tid & 31;
    uint32_t rank = ctarank();
    int bm0 = blockIdx.x * 128;          // this CTA's 128 rows (rank = x&1)
    int bn0 = blockIdx.y * TN;           // 256-wide N tile (shared by pair)

    if (wid == 0) {
        TC_ALLOC_CG2(sb, 256);
        TC_RELINQ_CG2();
    }
    if (tid == 0) {
        MBAR_INIT(sb + 8, 2);  MBAR_INIT(sb + 16, 2);   // full (rank0's used)
        MBAR_INIT(sb + 24, 1); MBAR_INIT(sb + 32, 1);   // done (both, multicast)
    }
    __syncthreads();
    CLUSTER_SYNC();   // mbarriers visible cluster-wide before any arrival
    uint32_t tmem;
    asm volatile("ld.shared.b32 %0, [%1];" : "=r"(tmem) : "r"(sb));

    const int nc = K >> 5;

    auto issue_stage = [&](int t) {
        uint32_t ab = sb + 1024 + (t & 1) * STAGE;
        const float* Ag = A + (size_t)bm0 * K + t * 32;
        const float* Bg = BT + (size_t)(bn0 + rank * 128) * K + t * 32;
#pragma unroll
        for (int i = 0; i < 4; i++) {
            int idx = tid + 256 * i;
            int r = idx >> 3, f = idx & 7;
            uint32_t off = (uint32_t)(r * 128 + f * 16);
            off ^= (off >> 3) & 0x70;
            CP16(ab + off, Ag + (size_t)r * K + f * 4);
            CP16(ab + 16384 + off, Bg + (size_t)r * K + f * 4);
        }
        CP_COMMIT();
    };

    issue_stage(0);
    issue_stage(1);

    for (int t = 0; t < nc; t++) {
        int s = t & 1;
        if (t < nc - NST) { CP_WAIT1(); } else { CP_WAIT0(); }
        FENCE_ASYNC();
        __syncthreads();
        if (tid == 0) MBAR_ARRIVE_RANK0(sb + 8 + 8 * s);
        if (rank == 0 && wid == 0 && elect_one()) {
            MBAR_WAIT(sb + 8 + 8 * s, (t >> 1) & 1);   // both CTAs' stage ready
            uint32_t base = sb + 1024 + s * STAGE;
            uint64_t ad = make_desc(base);
            uint64_t bd = make_desc(base + 16384);
#pragma unroll
            for (int k = 0; k < 4; k++)
                mma_tf32_ss_cg2(tmem, ad + k * 2, bd + k * 2, IDESC_TF32_M256_N256,
                                (t > 0 || k > 0) ? 1u : 0u);
            TC_COMMIT_MC_CG2(sb + 24 + 8 * s, 0x3);
        }
        if (t + NST < nc) {
            MBAR_WAIT(sb + 24 + 8 * s, (t >> 1) & 1);  // MMA done: stage s free
            issue_stage(t + NST);
        }
    }
    for (int tt = nc - NST; tt < nc; tt++)
        MBAR_WAIT(sb + 24 + 8 * (tt & 1), (tt >> 1) & 1);
    TC_FENCE_AFTER();
    __syncthreads();

    // epilogue: warps 0-3 read this CTA's 256 TMEM cols (its 128 D-rows)
    float cm = 1.f;
    if (QKVSCALE) cm = (bn0 < DD) ? 0.125f : 1.f;
    if (tid < 128) {
        float* tw = reinterpret_cast<float*>(smem + 1024) + wid * (32 * 33 + 8);
#pragma unroll
        for (int cb = 0; cb < TN; cb += 32) {
            uint32_t regs[32];
            TC_LD_X32(regs, tmem + cb);
            TC_WAIT_LD();
#pragma unroll
            for (int j = 0; j < 32; j++) tw[lid * 33 + j] = __uint_as_float(regs[j]);
            __syncwarp();
            float bv = BIAS ? bias[bn0 + cb + lid] : 0.f;
#pragma unroll 4
            for (int r = 0; r < 32; r++) {
                int row = bm0 + wid * 32 + r;
                int col = bn0 + cb + lid;
                float v = tw[r * 33 + lid];
                if (TF32OUT) v = to_tf32(v * cm);
                if (BIAS) v += bv;
                if (RELU) v = to_tf32(fmaxf(v, 0.f));   // FFN1 out feeds FFN2 A
                if (RES) v += res[(size_t)row * N + col];
                C[(size_t)row * N + col] = v;
            }
            __syncwarp();
        }
    }
    TC_FENCE_BEFORE();
    __syncthreads();
    CLUSTER_SYNC();   // peer may still read my smem/TMEM until its epilogue done
    if (wid == 0) TC_DEALLOC_CG2(tmem, 256);
#else
    // SIMT fallback (plain sm_103 pass; not expected to be selected)
    extern __shared__ char smem[];
    float* As = reinterpret_cast<float*>(smem);
    float* Bs = As + 16 * 128;
    int tid = threadIdx.x;
    int bm0 = blockIdx.x * 128;
    int tx = tid & 15, ty = tid >> 4;
    for (int nh = 0; nh < TN / 128; nh++) {
        int bn0 = blockIdx.y * TN + nh * 128;
        float cm = 1.f;
        if (QKVSCALE) cm = (bn0 < DD) ? 0.125f : 1.f;
        float acc[8][8];
#pragma unroll
        for (int i = 0; i < 8; i++)
#pragma unroll
            for (int j = 0; j < 8; j++) acc[i][j] = 0.f;
        for (int kt = 0; kt < K; kt += 16) {
            __syncthreads();
#pragma unroll
            for (int i = 0; i < 2; i++) {
                int idx = tid + 256 * i;
                int r = idx >> 2, c4 = (idx & 3) << 2;
                float4 va = *reinterpret_cast<const float4*>(&A[(size_t)(bm0 + r) * K + kt + c4]);
                As[(c4 + 0) * 128 + r] = va.x;
                As[(c4 + 1) * 128 + r] = va.y;
                As[(c4 + 2) * 128 + r] = va.z;
                As[(c4 + 3) * 128 + r] = va.w;
                float4 vb = *reinterpret_cast<const float4*>(&BT[(size_t)(bn0 + r) * K + kt + c4]);
                Bs[(c4 + 0) * 128 + r] = vb.x;
                Bs[(c4 + 1) * 128 + r] = vb.y;
                Bs[(c4 + 2) * 128 + r] = vb.z;
                Bs[(c4 + 3) * 128 + r] = vb.w;
            }
            __syncthreads();
#pragma unroll
            for (int k = 0; k < 16; k++) {
                float4 a0 = *reinterpret_cast<const float4*>(&As[k * 128 + ty * 4]);
                float4 a1 = *reinterpret_cast<const float4*>(&As[k * 128 + 64 + ty * 4]);
                float4 b0 = *reinterpret_cast<const float4*>(&Bs[k * 128 + tx * 4]);
                float4 b1 = *reinterpret_cast<const float4*>(&Bs[k * 128 + 64 + tx * 4]);
                float a[8] = {a0.x, a0.y, a0.z, a0.w, a1.x, a1.y, a1.z, a1.w};
                float bb[8] = {b0.x, b0.y, b0.z, b0.w, b1.x, b1.y, b1.z, b1.w};
#pragma unroll
                for (int i = 0; i < 8; i++)
#pragma unroll
                    for (int j = 0; j < 8; j++) acc[i][j] = fmaf(a[i], bb[j], acc[i][j]);
            }
        }
#pragma unroll
        for (int i = 0; i < 8; i++) {
            int row = bm0 + ((i < 4) ? (ty * 4 + i) : (64 + ty * 4 + i - 4));
#pragma unroll
            for (int j = 0; j < 8; j++) {
                int col = bn0 + ((j < 4) ? (tx * 4 + j) : (64 + tx * 4 + j - 4));
                float v = acc[i][j];
                if (TF32OUT) v = to_tf32(v * cm);
                if (BIAS) v += bias[col];
                if (RELU) v = fmaxf(v, 0.f);
                if (RES) v += res[(size_t)row * N + col];
                C[(size_t)row * N + col] = v;
            }
        }
        __syncthreads();
    }
#endif
}

// ---------------- tcgen05 attention (unchanged from R10) ----------------------
#define AT_Q 2048u
#define AT_K(buf) (34816u + (buf) * 32768u)
#define AT_V(buf) (100352u + (buf) * 32768u)
#define AT_P 165888u
#define ATTN_TC_SMEM 231424

__global__ __launch_bounds__(256)
void attn_tc(const float* __restrict__ Q, const float* __restrict__ K,
             const float* __restrict__ vT, float* __restrict__ O) {
#if HAS_TCGEN05
    extern __shared__ char smem[];
    uint32_t sb = smem_u32(smem);
    int tid = threadIdx.x;
    int wid = tid >> 5, lane = tid & 31;
    int b = blockIdx.z, h = blockIdx.y;
    int q0 = blockIdx.x * 128;

    if (wid == 0) {
        TC_ALLOC(sb, 256);
        TC_RELINQ();
    }
    if (tid == 0) { MBAR_INIT(sb + 8, 1); MBAR_INIT(sb + 16, 1); }
    __syncthreads();
    uint32_t tmem;
    asm volatile("ld.shared.b32 %0, [%1];" : "=r"(tmem) : "r"(sb));
    uint32_t tmem_S = tmem;
    uint32_t tmem_O = tmem + 128;

    auto issue_kv = [&](int t) {
        int buf = t & 1;
        const float* Kp = K + (size_t)(b * SS + t * 128) * QSTR + h * 64;
#pragma unroll
        for (int i = 0; i < 8; i++) {
            int idx = tid + 256 * i;
            int r = idx >> 4, f = idx & 15;
            uint32_t byte = (uint32_t)(((r >> 3) + (f >> 3) * 16) * 1024 +
                                       (r & 7) * 128 + (f & 7) * 16);
            byte ^= (byte >> 3) & 0x70;
            CP16(sb + AT_K(buf) + byte, Kp + (size_t)r * QSTR + f * 4);
        }
        const float* Vp = vT + ((size_t)(b * HH + h) * DK) * SS + t * 128;
#pragma unroll
        for (int i = 0; i < 8; i++) {
            int idx = tid + 256 * i;
            int d = idx >> 5, f = idx & 31;
            uint32_t byte = (uint32_t)(((d >> 3) + (f >> 3) * 8) * 1024 +
                                       (d & 7) * 128 + (f & 7) * 16);
            byte ^= (byte >> 3) & 0x70;
            CP16(sb + AT_V(buf) + byte, Vp + (size_t)d * SS + f * 4);
        }
        CP_COMMIT();
    };

    {
        const float* Qp = Q + (size_t)(b * SS + q0) * QSTR + h * 64;
#pragma unroll
        for (int i = 0; i < 8; i++) {
            int idx = tid + 256 * i;
            int r = idx >> 4, f = idx & 15;
            uint32_t byte = (uint32_t)(((r >> 3) + (f >> 3) * 16) * 1024 +
                                       (r & 7) * 128 + (f & 7) * 16);
            byte ^= (byte >> 3) & 0x70;
            CP16(sb + AT_Q + byte, Qp + (size_t)r * QSTR + f * 4);
        }
        issue_kv(0);
    }

    uint64_t descQ = make_desc(sb + AT_Q);
    float rsum = 0.f;
    const int sp = wid & 3;
    const int srow = sp * 32 + lane;
    const int colbase = (wid >> 2) * 64;

    for (int t = 0; t < 16; t++) {
        if (t > 0) MBAR_WAIT(sb + 16, (t - 1) & 1);
        if (t + 1 < 16) { issue_kv(t + 1); CP_WAIT1(); } else { CP_WAIT0(); }
        FENCE_ASYNC();
        __syncthreads();

        int buf = t & 1;
        if (wid == 0 && elect_one()) {
            uint64_t descK = make_desc(sb + AT_K(buf));
#pragma unroll
            for (int k = 0; k < 8; k++)
                mma_tf32_ss(tmem_S,
                            descQ + (k >> 2) * 1024 + (k & 3) * 2,
                            descK + (k >> 2) * 1024 + (k & 3) * 2,
                            IDESC_TF32_N128, k > 0 ? 1u : 0u);
            TC_COMMIT(sb + 8);
        }
        MBAR_WAIT(sb + 8, t & 1);
        TC_FENCE_AFTER();

#pragma unroll
        for (int cb2 = 0; cb2 < 64; cb2 += 32) {
            uint32_t regs[32];
            TC_LD_X32(regs, tmem_S + colbase + cb2);
            TC_WAIT_LD();
            float e[32];
#pragma unroll
            for (int j = 0; j < 32; j++) {
                e[j] = __expf(__uint_as_float(regs[j]));
                rsum += e[j];
            }
#pragma unroll
            for (int j0 = 0; j0 < 32; j0 += 4) {
                float4 v;
                v.x = to_tf32(e[j0 + 0]); v.y = to_tf32(e[j0 + 1]);
                v.z = to_tf32(e[j0 + 2]); v.w = to_tf32(e[j0 + 3]);
                int c = colbase + cb2 + j0;
                uint32_t byte = (uint32_t)(((srow >> 3) + (c >> 5) * 16) * 1024 +
                                           (srow & 7) * 128 + (c & 31) * 4);
                byte ^= (byte >> 3) & 0x70;
                *reinterpret_cast<float4*>(smem + AT_P + byte) = v;
            }
        }
        FENCE_ASYNC();
        __syncthreads();

        if (wid == 0 && elect_one()) {
            uint64_t descP = make_desc(sb + AT_P);
            uint64_t descV = make_desc(sb + AT_V(buf));
#pragma unroll
            for (int k = 0; k < 16; k++)
                mma_tf32_ss(tmem_O,
                            descP + (k >> 2) * 1024 + (k & 3) * 2,
                            descV + (k >> 2) * 512 + (k & 3) * 2,
                            IDESC_TF32_N64, (t > 0 || k > 0) ? 1u : 0u);
            TC_COMMIT(sb + 16);
        }
    }
    MBAR_WAIT(sb + 16, 15 & 1);
    TC_FENCE_AFTER();

    float* rs = reinterpret_cast<float*>(smem + 1024);
    rs[wid * 32 + lane] = rsum;
    __syncthreads();

    float* ob = reinterpret_cast<float*>(smem + AT_P);
    if (wid < 4) {
        float inv = 1.f / (rs[wid * 32 + lane] + rs[(wid + 4) * 32 + lane]);
        uint32_t r0[32], r1[32];
        TC_LD_X32(r0, tmem_O);
        TC_LD_X32(r1, tmem_O + 32);
        TC_WAIT_LD();
#pragma unroll
        for (int j = 0; j < 32; j++) {
            ob[srow * 68 + j] = to_tf32(__uint_as_float(r0[j]) * inv);
            ob[srow * 68 + 32 + j] = to_tf32(__uint_as_float(r1[j]) * inv);
        }
    }
    TC_FENCE_BEFORE();
    __syncthreads();
#pragma unroll
    for (int p = 0; p < 8; p++) {
        int slot = tid + 256 * p;
        int r = slot >> 4, f = slot & 15;
        float4 v = *reinterpret_cast<const float4*>(ob + r * 68 + f * 4);
        *reinterpret_cast<float4*>(O + (size_t)(b * SS + q0 + r) * DD + h * 64 + f * 4) = v;
    }
    __syncthreads();
    if (wid == 0) TC_DEALLOC(tmem, 256);
#else
    int tid = threadIdx.x;
    int b = blockIdx.z, h = blockIdx.y;
    int q0 = blockIdx.x * 128;
    int r = tid >> 1, dh = (tid & 1) * 32;
    const float* qp = Q + (size_t)(b * SS + q0 + r) * QSTR + h * 64;
    float acc[32];
#pragma unroll
    for (int j = 0; j < 32; j++) acc[j] = 0.f;
    float l = 0.f;
    for (int kv = 0; kv < SS; kv++) {
        const float* kp = K + (size_t)(b * SS + kv) * QSTR + h * 64;
        float s = 0.f;
        for (int d = 0; d < 64; d++) s += qp[d] * kp[d];
        float e = __expf(s);
        l += e;
        const float* vp = vT + ((size_t)(b * HH + h) * DK + dh) * SS + kv;
        for (int j = 0; j < 32; j++) acc[j] += e * vp[(size_t)j * SS];
    }
    float inv = 1.f / l;
    float* op = O + (size_t)(b * SS + q0 + r) * DD + h * 64 + dh;
    for (int j = 0; j < 32; j++) op[j] = acc[j] * inv;
#endif
}

// ---------------- launch -------------------------------------------------------
extern "C" void kernel_launch(void* const* d_in, const int* in_sizes, int n_in,
                              void* d_out, int out_size) {
    const float* x   = (const float*)d_in[0];
    const float* wq  = (const float*)d_in[1];
    const float* wk  = (const float*)d_in[2];
    const float* wv  = (const float*)d_in[3];
    const float* wo  = (const float*)d_in[4];
    const float* w1  = (const float*)d_in[5];
    const float* b1  = (const float*)d_in[6];
    const float* w2  = (const float*)d_in[7];
    const float* b2  = (const float*)d_in[8];
    const float* g1  = (const float*)d_in[9];
    const float* be1 = (const float*)d_in[10];
    const float* g2  = (const float*)d_in[11];
    const float* be2 = (const float*)d_in[12];
    float* out = (float*)d_out;

    float *h, *qkv, *attn, *x1, *ffn, *vT;
    float *wqkvT, *woT, *w1T, *w2T;
    cudaGetSymbolAddress((void**)&h, g_h);
    cudaGetSymbolAddress((void**)&qkv, g_qkv);
    cudaGetSymbolAddress((void**)&attn, g_attn);
    cudaGetSymbolAddress((void**)&x1, g_x1);
    cudaGetSymbolAddress((void**)&ffn, g_ffn);
    cudaGetSymbolAddress((void**)&vT, g_vT);
    cudaGetSymbolAddress((void**)&wqkvT, g_wqkvT);
    cudaGetSymbolAddress((void**)&woT, g_woT);
    cudaGetSymbolAddress((void**)&w1T, g_w1T);
    cudaGetSymbolAddress((void**)&w2T, g_w2T);

    static bool attr_done = false;
    if (!attr_done) {
        cudaFuncSetAttribute(attn_tc,
                             cudaFuncAttributeMaxDynamicSharedMemorySize, ATTN_TC_SMEM);
        cudaFuncSetAttribute(gemm_tc<false, false, false, true, true>,
                             cudaFuncAttributeMaxDynamicSharedMemorySize, GT_SMEM);
        cudaFuncSetAttribute(gemm_tc<false, false, true, false, false>,
                             cudaFuncAttributeMaxDynamicSharedMemorySize, GT_SMEM);
        cudaFuncSetAttribute(gemm_tc<true, true, false, false, false>,
                             cudaFuncAttributeMaxDynamicSharedMemorySize, GT_SMEM);
        cudaFuncSetAttribute(gemm_tc<true, false, true, false, false>,
                             cudaFuncAttributeMaxDynamicSharedMemorySize, GT_SMEM);
        attr_done = true;
    }

    // weight transposes -> [N, K], tf32-rounded; qkv weights concatenated
    transpose_kernel<<<dim3(DD / 32, DD / 32), 256>>>(wq, wqkvT, DD, DD);
    transpose_kernel<<<dim3(DD / 32, DD / 32), 256>>>(wk, wqkvT + (size_t)DD * DD, DD, DD);
    transpose_kernel<<<dim3(DD / 32, DD / 32), 256>>>(wv, wqkvT + (size_t)2 * DD * DD, DD, DD);
    transpose_kernel<<<dim3(DD / 32, DD / 32), 256>>>(wo, woT, DD, DD);
    transpose_kernel<<<dim3(DFF / 32, DD / 32), 256>>>(w1, w1T, DD, DFF);
    transpose_kernel<<<dim3(DD / 32, DFF / 32), 256>>>(w2, w2T, DFF, DD);

    // grid: x = M tiles (128 rows, cluster pairs along x), y = N tiles (256)
    dim3 gQKV(NT / 128, 3 * DD / TN);   // (64, 12)
    dim3 gWo(NT / 128, DD / TN);        // (64, 4)
    dim3 gF1(NT / 128, DFF / TN);       // (64, 16)
    dim3 gF2(NT / 128, DD / TN);        // (64, 4)

    ln_kernel<<<NT / 8, 256>>>(x, g1, be1, h);
    gemm_tc<false, false, false, true, true><<<gQKV, 256, GT_SMEM>>>(
        h, wqkvT, nullptr, nullptr, qkv, 3 * DD, DD);
    vt_kernel<<<dim3(SS / 32, DK / 32, BB * HH), 256>>>(qkv + 2 * DD, vT);
    attn_tc<<<dim3(SS / 128, HH, BB), 256, ATTN_TC_SMEM>>>(qkv, qkv + DD, vT, attn);
    gemm_tc<false, false, true, false, false><<<gWo, 256, GT_SMEM>>>(
        attn, woT, nullptr, x, x1, DD, DD);
    ln_kernel<<<NT / 8, 256>>>(x1, g2, be2, h);
    gemm_tc<true, true, false, false, false><<<gF1, 256, GT_SMEM>>>(
        h, w1T, b1, nullptr, ffn, DFF, DD);
    gemm_tc<true, false, true, false, false><<<gF2, 256, GT_SMEM>>>(
        ffn, w2T, b2, x1, out, DD, DFF);
}

// round 13
// speedup vs baseline: 1.6270x; 1.6270x over previous
#include <cuda_runtime.h>
#include <cuda_bf16.h>
#include <math.h>
#include <cstdint>

// Problem constants
#define BB 4
#define SS 2048
#define DD 1024
#define HH 16
#define DK 64
#define DFF 4096
#define NT (BB * SS)   // 8192 tokens
#define EPS 1e-5f
#define QSTR (3 * DD)  // row stride of fused qkv buffer

// Does this compilation pass have sm_103a-specific (tcgen05) features?
#if !defined(__CUDA_ARCH__) || defined(__CUDA_ARCH_FEAT_SM103_ALL) || \
    defined(__CUDA_ARCH_FEAT_SM100_ALL) || defined(__CUDA_ARCH_SPECIFIC__)
#define HAS_TCGEN05 1
#else
#define HAS_TCGEN05 0
#endif

// ---------------- scratch (device globals; no allocs allowed) ----------------
__device__ float g_h[(size_t)NT * DD];
__device__ float g_qkv[(size_t)NT * 3 * DD];   // fused q|k|v, row stride 3072
__device__ float g_attn[(size_t)NT * DD];
__device__ float g_x1[(size_t)NT * DD];
__device__ float g_ffn[(size_t)NT * DFF];
__device__ float g_vT[(size_t)BB * HH * DK * SS];   // [b,h,dk,s]
// transposed weights [N, K] (tf32-rounded); wqkvT = concat(wqT, wkT, wvT)
__device__ float g_wqkvT[(size_t)3 * DD * DD];
__device__ float g_woT[(size_t)DD * DD];
__device__ float g_w1T[(size_t)DFF * DD];
__device__ float g_w2T[(size_t)DD * DFF];

// ---------------- PTX helpers --------------------------------------------------
__device__ __forceinline__ uint32_t smem_u32(const void* p) {
    uint32_t a;
    asm("{ .reg .u64 t; cvta.to.shared.u64 t, %1; cvt.u32.u64 %0, t; }"
        : "=r"(a) : "l"(p));
    return a;
}
__device__ __forceinline__ uint32_t elect_one() {
    uint32_t p;
    asm volatile("{ .reg .pred p; elect.sync _|p, 0xFFFFFFFF; selp.b32 %0,1,0,p; }"
                 : "=r"(p));
    return p;
}
__device__ __forceinline__ float to_tf32(float x) {
    uint32_t u;
    asm("cvt.rna.tf32.f32 %0, %1;" : "=r"(u) : "f"(x));
    return __uint_as_float(u);
}
#define MBAR_INIT(a, c) \
    asm volatile("mbarrier.init.shared.b64 [%0], %1;" :: "r"((uint32_t)(a)), "r"((uint32_t)(c)) : "memory")
#define MBAR_WAIT(a, par) do {                                                   \
    uint32_t _m = (uint32_t)(a); uint32_t _p = (uint32_t)(par); uint32_t _d;     \
    asm volatile("{ .reg .pred p; mbarrier.try_wait.parity.acquire.cta.shared::cta.b64 p, [%1], %2;" \
                 " selp.b32 %0,1,0,p; }" : "=r"(_d) : "r"(_m), "r"(_p) : "memory"); \
    if (!_d) {                                                                   \
        asm volatile("{ .reg .pred P1; WL_%=: mbarrier.try_wait.parity.acquire.cta.shared::cta.b64 P1, [%0], %1, 0x989680;" \
                     " @P1 bra.uni WD_%=; bra.uni WL_%=; WD_%=: }"               \
                     :: "r"(_m), "r"(_p) : "memory");                            \
    } } while (0)
#define CP16(dst, src) \
    asm volatile("cp.async.cg.shared.global [%0], [%1], 16;" \
                 :: "r"((uint32_t)(dst)), "l"(src) : "memory")
#define CP_COMMIT() asm volatile("cp.async.commit_group;" ::: "memory")
#define CP_WAIT1()  asm volatile("cp.async.wait_group 1;" ::: "memory")
#define CP_WAIT0()  asm volatile("cp.async.wait_group 0;" ::: "memory")
#define FENCE_ASYNC() asm volatile("fence.proxy.async.shared::cta;" ::: "memory")

#if HAS_TCGEN05
#define TC_ALLOC(smem_addr, n) \
    asm volatile("tcgen05.alloc.cta_group::1.sync.aligned.shared::cta.b32 [%0], %1;" \
                 :: "r"((uint32_t)(smem_addr)), "r"((uint32_t)(n)) : "memory")
#define TC_DEALLOC(tmem, n) \
    asm volatile("tcgen05.dealloc.cta_group::1.sync.aligned.b32 %0, %1;" \
                 :: "r"(tmem), "r"((uint32_t)(n)))
#define TC_RELINQ() \
    asm volatile("tcgen05.relinquish_alloc_permit.cta_group::1.sync.aligned;")
#define TC_COMMIT(mbar) \
    asm volatile("tcgen05.commit.cta_group::1.mbarrier::arrive::one.shared::cluster.b64 [%0];" \
                 :: "r"((uint32_t)(mbar)) : "memory")
#define TC_WAIT_LD() asm volatile("tcgen05.wait::ld.sync.aligned;" ::: "memory")
#define TC_FENCE_BEFORE() asm volatile("tcgen05.fence::before_thread_sync;" ::: "memory")
#define TC_FENCE_AFTER()  asm volatile("tcgen05.fence::after_thread_sync;" ::: "memory")
#define TC_LD_X32(r, tmem)                                                        \
    asm volatile("tcgen05.ld.sync.aligned.32x32b.x32.b32 "                        \
        "{%0,%1,%2,%3,%4,%5,%6,%7,%8,%9,%10,%11,%12,%13,%14,%15,"                 \
        "%16,%17,%18,%19,%20,%21,%22,%23,%24,%25,%26,%27,%28,%29,%30,%31}, [%32];"\
        : "=r"((r)[0]),"=r"((r)[1]),"=r"((r)[2]),"=r"((r)[3]),                    \
          "=r"((r)[4]),"=r"((r)[5]),"=r"((r)[6]),"=r"((r)[7]),                    \
          "=r"((r)[8]),"=r"((r)[9]),"=r"((r)[10]),"=r"((r)[11]),                  \
          "=r"((r)[12]),"=r"((r)[13]),"=r"((r)[14]),"=r"((r)[15]),                \
          "=r"((r)[16]),"=r"((r)[17]),"=r"((r)[18]),"=r"((r)[19]),                \
          "=r"((r)[20]),"=r"((r)[21]),"=r"((r)[22]),"=r"((r)[23]),                \
          "=r"((r)[24]),"=r"((r)[25]),"=r"((r)[26]),"=r"((r)[27]),                \
          "=r"((r)[28]),"=r"((r)[29]),"=r"((r)[30]),"=r"((r)[31])                 \
        : "r"(tmem))

static constexpr uint64_t DESC_SW128 =
    (uint64_t(2) << 61) | (uint64_t(1) << 46) | (uint64_t(64) << 32) | (uint64_t(1) << 16);
__device__ __forceinline__ uint64_t make_desc(uint32_t addr) {
    return DESC_SW128 | ((uint64_t)(addr >> 4) & 0x3FFF);
}
// tf32 idesc: c=F32(1<<4), a=TF32(2<<7), b=TF32(2<<10), M=128(8<<24), N<<17/8
#define IDESC_TF32_N128 0x8200910u
#define IDESC_TF32_N256 0x8400910u
#define IDESC_TF32_N64  0x8100910u
__device__ __forceinline__ void mma_tf32_ss(uint32_t d, uint64_t ad, uint64_t bd,
                                            uint32_t idesc, uint32_t en) {
    uint32_t zero = 0;
    asm volatile("{ .reg .pred p; setp.ne.u32 p, %6, 0;"
                 " tcgen05.mma.cta_group::1.kind::tf32 [%0], %1, %2, %3, "
                 "{%4, %4, %4, %4}, p; }"
                 :: "r"(d), "l"(ad), "l"(bd), "r"(idesc),
                    "r"(zero), "r"(zero), "r"(en) : "memory");
}
#endif  // HAS_TCGEN05

// ---------------- weight transpose: out[C][R] = tf32(in[R][C]) ----------------
__global__ __launch_bounds__(256) void transpose_kernel(const float* __restrict__ in,
                                                        float* __restrict__ out,
                                                        int R, int C) {
    __shared__ float t[32][33];
    int tx = threadIdx.x & 31, ty = threadIdx.x >> 5;  // 32 x 8
    int c0 = blockIdx.x * 32, r0 = blockIdx.y * 32;
#pragma unroll
    for (int i = 0; i < 4; i++)
        t[ty + 8 * i][tx] = in[(size_t)(r0 + ty + 8 * i) * C + c0 + tx];
    __syncthreads();
#pragma unroll
    for (int i = 0; i < 4; i++)
        out[(size_t)(c0 + ty + 8 * i) * R + r0 + tx] = to_tf32(t[tx][ty + 8 * i]);
}

// ---------------- v transpose (from fused qkv) -> vT[b,h,dk,s] ----------------
__global__ __launch_bounds__(256) void vt_kernel(const float* __restrict__ vsec,
                                                 float* __restrict__ vT) {
    __shared__ float t[32][33];
    int tx = threadIdx.x & 31, ty = threadIdx.x >> 5;
    int bh = blockIdx.z;
    int b = bh >> 4, h = bh & 15;
    int s0 = blockIdx.x * 32, d0 = blockIdx.y * 32;
#pragma unroll
    for (int i = 0; i < 4; i++)
        t[ty + 8 * i][tx] =
            vsec[(size_t)(b * SS + s0 + ty + 8 * i) * QSTR + h * 64 + d0 + tx];
    __syncthreads();
#pragma unroll
    for (int i = 0; i < 4; i++)
        vT[((size_t)bh * DK + d0 + ty + 8 * i) * SS + s0 + tx] = t[tx][ty + 8 * i];
}

// ---------------- LayerNorm: 1 warp per row, no block syncs -------------------
__global__ __launch_bounds__(256) void ln_kernel(const float* __restrict__ x,
                                                 const float* __restrict__ g,
                                                 const float* __restrict__ b,
                                                 float* __restrict__ out) {
    int w = threadIdx.x >> 5, lane = threadIdx.x & 31;
    int row = blockIdx.x * 8 + w;
    const float4* xr = reinterpret_cast<const float4*>(x + (size_t)row * DD);
    float4 v[8];
    float s = 0.f;
#pragma unroll
    for (int i = 0; i < 8; i++) {
        v[i] = xr[lane + 32 * i];
        s += v[i].x + v[i].y + v[i].z + v[i].w;
    }
#pragma unroll
    for (int o = 16; o > 0; o >>= 1) s += __shfl_xor_sync(~0u, s, o);
    float mu = s * (1.f / DD);
    float s2 = 0.f;
#pragma unroll
    for (int i = 0; i < 8; i++) {
        float dx = v[i].x - mu, dy = v[i].y - mu, dz = v[i].z - mu, dw = v[i].w - mu;
        s2 += dx * dx + dy * dy + dz * dz + dw * dw;
    }
#pragma unroll
    for (int o = 16; o > 0; o >>= 1) s2 += __shfl_xor_sync(~0u, s2, o);
    float rstd = rsqrtf(s2 * (1.f / DD) + EPS);
    const float4* gp = reinterpret_cast<const float4*>(g);
    const float4* bp = reinterpret_cast<const float4*>(b);
    float4* op = reinterpret_cast<float4*>(out + (size_t)row * DD);
#pragma unroll
    for (int i = 0; i < 8; i++) {
        float4 gg = gp[lane + 32 * i], bb = bp[lane + 32 * i], o;
        o.x = to_tf32((v[i].x - mu) * rstd * gg.x + bb.x);
        o.y = to_tf32((v[i].y - mu) * rstd * gg.y + bb.y);
        o.z = to_tf32((v[i].z - mu) * rstd * gg.z + bb.z);
        o.w = to_tf32((v[i].w - mu) * rstd * gg.w + bb.w);
        op[lane + 32 * i] = o;
    }
}

// ---------------- GEMM: C[M,N] = A[M,K] @ BT[N,K]^T (R10 proven config) -------
// Tile 128 x 256, 2-stage cp.async pipeline, K-chunk 32; 99328 B smem -> 2 CTA/SM.
// TF32OUT: C = tf32(acc * cm); QKVSCALE: cm = 0.125 for cols < DD (q section).
#define TN 256
#define NST 2
#define STAGE (16384 + TN * 128)
#define GT_SMEM (1024 + NST * STAGE)   // 99328

template <bool BIAS, bool RELU, bool RES, bool TF32OUT, bool QKVSCALE>
__global__ __launch_bounds__(256)
void gemm_tc(const float* __restrict__ A, const float* __restrict__ BT,
             const float* __restrict__ bias, const float* __restrict__ res,
             float* __restrict__ C, int N, int K) {
#if HAS_TCGEN05
    extern __shared__ char smem[];
    uint32_t sb = smem_u32(smem);
    int tid = threadIdx.x;
    int wid = tid >> 5, lid = tid & 31;
    int bm0 = blockIdx.y * 128, bn0 = blockIdx.x * TN;

    if (wid == 0) {
        TC_ALLOC(sb, TN);
        TC_RELINQ();
    }
    if (tid == 0) { MBAR_INIT(sb + 8, 1); MBAR_INIT(sb + 16, 1); }
    __syncthreads();
    uint32_t tmem;
    asm volatile("ld.shared.b32 %0, [%1];" : "=r"(tmem) : "r"(sb));

    const int nc = K >> 5;

    auto issue_stage = [&](int t) {
        int s = t % NST;
        uint32_t ab = sb + 1024 + s * STAGE;
        const float* Ag = A + (size_t)bm0 * K + t * 32;
        const float* Bg = BT + (size_t)bn0 * K + t * 32;
#pragma unroll
        for (int i = 0; i < 4; i++) {
            int idx = tid + 256 * i;
            int r = idx >> 3, f = idx & 7;
            uint32_t off = (uint32_t)(r * 128 + f * 16);
            off ^= (off >> 3) & 0x70;
            CP16(ab + off, Ag + (size_t)r * K + f * 4);
        }
#pragma unroll
        for (int i = 0; i < TN / 32; i++) {
            int idx = tid + 256 * i;
            int r = idx >> 3, f = idx & 7;
            uint32_t off = (uint32_t)(r * 128 + f * 16);
            off ^= (off >> 3) & 0x70;
            CP16(ab + 16384 + off, Bg + (size_t)r * K + f * 4);
        }
        CP_COMMIT();
    };

    issue_stage(0);
    issue_stage(1);

    for (int t = 0; t < nc; t++) {
        if (t < nc - NST) { CP_WAIT1(); } else { CP_WAIT0(); }
        FENCE_ASYNC();
        __syncthreads();
        if (wid == 0 && elect_one()) {
            uint32_t base = sb + 1024 + (t % NST) * STAGE;
            uint64_t ad = make_desc(base);
            uint64_t bd = make_desc(base + 16384);
#pragma unroll
            for (int k = 0; k < 4; k++)
                mma_tf32_ss(tmem, ad + k * 2, bd + k * 2, IDESC_TF32_N256,
                            (t > 0 || k > 0) ? 1u : 0u);
            TC_COMMIT(sb + 8 + 8 * (t % NST));
        }
        if (t + NST < nc) {
            MBAR_WAIT(sb + 8 + 8 * (t % NST), (t / NST) & 1);
            issue_stage(t + NST);
        }
    }
    for (int tt = nc - NST; tt < nc; tt++)
        MBAR_WAIT(sb + 8 + 8 * (tt % NST), (tt / NST) & 1);
    TC_FENCE_AFTER();
    __syncthreads();

    // epilogue: warps 0-3 read TMEM, transpose via smem, store coalesced
    float cm = 1.f;
    if (QKVSCALE) cm = (bn0 < DD) ? 0.125f : 1.f;
    if (tid < 128) {
        float* tw = reinterpret_cast<float*>(smem + 1024) + wid * (32 * 33 + 8);
#pragma unroll
        for (int cb = 0; cb < TN; cb += 32) {
            uint32_t regs[32];
            TC_LD_X32(regs, tmem + cb);
            TC_WAIT_LD();
#pragma unroll
            for (int j = 0; j < 32; j++) tw[lid * 33 + j] = __uint_as_float(regs[j]);
            __syncwarp();
            float bv = BIAS ? bias[bn0 + cb + lid] : 0.f;
#pragma unroll 4
            for (int r = 0; r < 32; r++) {
                int row = bm0 + wid * 32 + r;
                int col = bn0 + cb + lid;
                float v = tw[r * 33 + lid];
                if (TF32OUT) v = to_tf32(v * cm);
                if (BIAS) v += bv;
                if (RELU) v = to_tf32(fmaxf(v, 0.f));   // FFN1 out feeds FFN2 A
                if (RES) v += res[(size_t)row * N + col];
                C[(size_t)row * N + col] = v;
            }
            __syncwarp();
        }
    }
    TC_FENCE_BEFORE();
    __syncthreads();
    if (wid == 0) TC_DEALLOC(tmem, TN);
#else
    // SIMT fallback (plain sm_103 pass; not expected to be selected)
    extern __shared__ char smem[];
    float* As = reinterpret_cast<float*>(smem);
    float* Bs = As + 16 * 128;
    int tid = threadIdx.x;
    int bm0 = blockIdx.y * 128;
    int tx = tid & 15, ty = tid >> 4;
    for (int nh = 0; nh < TN / 128; nh++) {
        int bn0 = blockIdx.x * TN + nh * 128;
        float cm = 1.f;
        if (QKVSCALE) cm = (bn0 < DD) ? 0.125f : 1.f;
        float acc[8][8];
#pragma unroll
        for (int i = 0; i < 8; i++)
#pragma unroll
            for (int j = 0; j < 8; j++) acc[i][j] = 0.f;
        for (int kt = 0; kt < K; kt += 16) {
            __syncthreads();
#pragma unroll
            for (int i = 0; i < 2; i++) {
                int idx = tid + 256 * i;
                int r = idx >> 2, c4 = (idx & 3) << 2;
                float4 va = *reinterpret_cast<const float4*>(&A[(size_t)(bm0 + r) * K + kt + c4]);
                As[(c4 + 0) * 128 + r] = va.x;
                As[(c4 + 1) * 128 + r] = va.y;
                As[(c4 + 2) * 128 + r] = va.z;
                As[(c4 + 3) * 128 + r] = va.w;
                float4 vb = *reinterpret_cast<const float4*>(&BT[(size_t)(bn0 + r) * K + kt + c4]);
                Bs[(c4 + 0) * 128 + r] = vb.x;
                Bs[(c4 + 1) * 128 + r] = vb.y;
                Bs[(c4 + 2) * 128 + r] = vb.z;
                Bs[(c4 + 3) * 128 + r] = vb.w;
            }
            __syncthreads();
#pragma unroll
            for (int k = 0; k < 16; k++) {
                float4 a0 = *reinterpret_cast<const float4*>(&As[k * 128 + ty * 4]);
                float4 a1 = *reinterpret_cast<const float4*>(&As[k * 128 + 64 + ty * 4]);
                float4 b0 = *reinterpret_cast<const float4*>(&Bs[k * 128 + tx * 4]);
                float4 b1 = *reinterpret_cast<const float4*>(&Bs[k * 128 + 64 + tx * 4]);
                float a[8] = {a0.x, a0.y, a0.z, a0.w, a1.x, a1.y, a1.z, a1.w};
                float bb[8] = {b0.x, b0.y, b0.z, b0.w, b1.x, b1.y, b1.z, b1.w};
#pragma unroll
                for (int i = 0; i < 8; i++)
#pragma unroll
                    for (int j = 0; j < 8; j++) acc[i][j] = fmaf(a[i], bb[j], acc[i][j]);
            }
        }
#pragma unroll
        for (int i = 0; i < 8; i++) {
            int row = bm0 + ((i < 4) ? (ty * 4 + i) : (64 + ty * 4 + i - 4));
#pragma unroll
            for (int j = 0; j < 8; j++) {
                int col = bn0 + ((j < 4) ? (tx * 4 + j) : (64 + tx * 4 + j - 4));
                float v = acc[i][j];
                if (TF32OUT) v = to_tf32(v * cm);
                if (BIAS) v += bias[col];
                if (RELU) v = fmaxf(v, 0.f);
                if (RES) v += res[(size_t)row * N + col];
                C[(size_t)row * N + col] = v;
            }
        }
        __syncthreads();
    }
#endif
}

// ---------------- tcgen05 attention: S double-buffered in TMEM ----------------
// grid (S/128, H, B), 256 threads. TMEM: S0@0, S1@128, O@256 (alloc 512).
// Per iteration: wait S(t) -> softmax(t) -> sync -> issue PV(t) + S(t+1)
// back-to-back (in-order completion makes S(t+1)-commit imply PV(t)-done for
// the P buffer) -> wait PV(t) -> prefetch kv(t+2).
#define AT_Q 2048u
#define AT_K(buf) (34816u + (buf) * 32768u)
#define AT_V(buf) (100352u + (buf) * 32768u)
#define AT_P 165888u
#define ATTN_TC_SMEM 231424

__global__ __launch_bounds__(256)
void attn_tc(const float* __restrict__ Q, const float* __restrict__ K,
             const float* __restrict__ vT, float* __restrict__ O) {
#if HAS_TCGEN05
    extern __shared__ char smem[];
    uint32_t sb = smem_u32(smem);
    int tid = threadIdx.x;
    int wid = tid >> 5, lane = tid & 31;
    int b = blockIdx.z, h = blockIdx.y;
    int q0 = blockIdx.x * 128;

    if (wid == 0) {
        TC_ALLOC(sb, 512);
        TC_RELINQ();
    }
    if (tid == 0) { MBAR_INIT(sb + 8, 1); MBAR_INIT(sb + 16, 1); }
    __syncthreads();
    uint32_t tmem;
    asm volatile("ld.shared.b32 %0, [%1];" : "=r"(tmem) : "r"(sb));
    uint32_t tmem_O = tmem + 256;

    auto issue_kv = [&](int t) {
        int buf = t & 1;
        const float* Kp = K + (size_t)(b * SS + t * 128) * QSTR + h * 64;
#pragma unroll
        for (int i = 0; i < 8; i++) {
            int idx = tid + 256 * i;
            int r = idx >> 4, f = idx & 15;
            uint32_t byte = (uint32_t)(((r >> 3) + (f >> 3) * 16) * 1024 +
                                       (r & 7) * 128 + (f & 7) * 16);
            byte ^= (byte >> 3) & 0x70;
            CP16(sb + AT_K(buf) + byte, Kp + (size_t)r * QSTR + f * 4);
        }
        const float* Vp = vT + ((size_t)(b * HH + h) * DK) * SS + t * 128;
#pragma unroll
        for (int i = 0; i < 8; i++) {
            int idx = tid + 256 * i;
            int d = idx >> 5, f = idx & 31;
            uint32_t byte = (uint32_t)(((d >> 3) + (f >> 3) * 8) * 1024 +
                                       (d & 7) * 128 + (f & 7) * 16);
            byte ^= (byte >> 3) & 0x70;
            CP16(sb + AT_V(buf) + byte, Vp + (size_t)d * SS + f * 4);
        }
        CP_COMMIT();
    };

    uint64_t descQ = make_desc(sb + AT_Q);

    auto s_mma = [&](int t) {   // S(t) = Q @ K(t)^T -> tmem S[t&1]
        uint64_t descK = make_desc(sb + AT_K(t & 1));
        uint32_t dst = tmem + (t & 1) * 128;
#pragma unroll
        for (int k = 0; k < 8; k++)
            mma_tf32_ss(dst,
                        descQ + (k >> 2) * 1024 + (k & 3) * 2,
                        descK + (k >> 2) * 1024 + (k & 3) * 2,
                        IDESC_TF32_N128, k > 0 ? 1u : 0u);
        TC_COMMIT(sb + 8);
    };

    // prologue: Q + kv(0); wait; S(0); prefetch kv(1)
    {
        const float* Qp = Q + (size_t)(b * SS + q0) * QSTR + h * 64;
#pragma unroll
        for (int i = 0; i < 8; i++) {
            int idx = tid + 256 * i;
            int r = idx >> 4, f = idx & 15;
            uint32_t byte = (uint32_t)(((r >> 3) + (f >> 3) * 16) * 1024 +
                                       (r & 7) * 128 + (f & 7) * 16);
            byte ^= (byte >> 3) & 0x70;
            CP16(sb + AT_Q + byte, Qp + (size_t)r * QSTR + f * 4);
        }
        issue_kv(0);
        CP_WAIT0();
        FENCE_ASYNC();
        __syncthreads();
        if (wid == 0 && elect_one()) s_mma(0);
        issue_kv(1);
    }

    float rsum = 0.f;
    const int sp = wid & 3;
    const int srow = sp * 32 + lane;
    const int colbase = (wid >> 2) * 64;

    for (int t = 0; t < 16; t++) {
        MBAR_WAIT(sb + 8, t & 1);     // S(t) done (implies PV(t-1) done too)
        TC_FENCE_AFTER();

        // softmax(t): all 8 warps; warp w handles cols [colbase, colbase+64)
        uint32_t tS = tmem + (t & 1) * 128;
#pragma unroll
        for (int cb2 = 0; cb2 < 64; cb2 += 32) {
            uint32_t regs[32];
            TC_LD_X32(regs, tS + colbase + cb2);
            TC_WAIT_LD();
            float e[32];
#pragma unroll
            for (int j = 0; j < 32; j++) {
                e[j] = __expf(__uint_as_float(regs[j]));
                rsum += e[j];
            }
#pragma unroll
            for (int j0 = 0; j0 < 32; j0 += 4) {
                float4 v;
                v.x = to_tf32(e[j0 + 0]); v.y = to_tf32(e[j0 + 1]);
                v.z = to_tf32(e[j0 + 2]); v.w = to_tf32(e[j0 + 3]);
                int c = colbase + cb2 + j0;
                uint32_t byte = (uint32_t)(((srow >> 3) + (c >> 5) * 16) * 1024 +
                                           (srow & 7) * 128 + (c & 31) * 4);
                byte ^= (byte >> 3) & 0x70;
                *reinterpret_cast<float4*>(smem + AT_P + byte) = v;
            }
        }
        CP_WAIT0();       // kv(t+1) resident (no-op at t=15)
        FENCE_ASYNC();
        __syncthreads();  // P ready + kv(t+1) visible

        if (wid == 0 && elect_one()) {
            // PV(t): O += P @ V(t)^T
            uint64_t descP = make_desc(sb + AT_P);
            uint64_t descV = make_desc(sb + AT_V(t & 1));
#pragma unroll
            for (int k = 0; k < 16; k++)
                mma_tf32_ss(tmem_O,
                            descP + (k >> 2) * 1024 + (k & 3) * 2,
                            descV + (k >> 2) * 512 + (k & 3) * 2,
                            IDESC_TF32_N64, (t > 0 || k > 0) ? 1u : 0u);
            TC_COMMIT(sb + 16);
            if (t < 15) s_mma(t + 1);   // S(t+1) queued behind PV(t)
        }
        if (t < 15) {
            MBAR_WAIT(sb + 16, t & 1);  // PV(t) done: buf t&1 free
            if (t + 2 < 16) issue_kv(t + 2);
        }
    }
    MBAR_WAIT(sb + 16, 15 & 1);
    TC_FENCE_AFTER();

    // combine per-warp rsum partials (warps w and w+4 share rows)
    float* rs = reinterpret_cast<float*>(smem + 1024);
    rs[wid * 32 + lane] = rsum;
    __syncthreads();

    // epilogue: tf32-round O (feeds Wo-GEMM A operand)
    float* ob = reinterpret_cast<float*>(smem + AT_P);
    if (wid < 4) {
        float inv = 1.f / (rs[wid * 32 + lane] + rs[(wid + 4) * 32 + lane]);
        uint32_t r0[32], r1[32];
        TC_LD_X32(r0, tmem_O);
        TC_LD_X32(r1, tmem_O + 32);
        TC_WAIT_LD();
#pragma unroll
        for (int j = 0; j < 32; j++) {
            ob[srow * 68 + j] = to_tf32(__uint_as_float(r0[j]) * inv);
            ob[srow * 68 + 32 + j] = to_tf32(__uint_as_float(r1[j]) * inv);
        }
    }
    TC_FENCE_BEFORE();
    __syncthreads();
#pragma unroll
    for (int p = 0; p < 8; p++) {
        int slot = tid + 256 * p;
        int r = slot >> 4, f = slot & 15;
        float4 v = *reinterpret_cast<const float4*>(ob + r * 68 + f * 4);
        *reinterpret_cast<float4*>(O + (size_t)(b * SS + q0 + r) * DD + h * 64 + f * 4) = v;
    }
    __syncthreads();
    if (wid == 0) TC_DEALLOC(tmem, 512);
#else
    // naive SIMT fallback (q pre-scaled by 1/8; qkv strided)
    int tid = threadIdx.x;
    int b = blockIdx.z, h = blockIdx.y;
    int q0 = blockIdx.x * 128;
    int r = tid >> 1, dh = (tid & 1) * 32;
    const float* qp = Q + (size_t)(b * SS + q0 + r) * QSTR + h * 64;
    float acc[32];
#pragma unroll
    for (int j = 0; j < 32; j++) acc[j] = 0.f;
    float l = 0.f;
    for (int kv = 0; kv < SS; kv++) {
        const float* kp = K + (size_t)(b * SS + kv) * QSTR + h * 64;
        float s = 0.f;
        for (int d = 0; d < 64; d++) s += qp[d] * kp[d];
        float e = __expf(s);
        l += e;
        const float* vp = vT + ((size_t)(b * HH + h) * DK + dh) * SS + kv;
        for (int j = 0; j < 32; j++) acc[j] += e * vp[(size_t)j * SS];
    }
    float inv = 1.f / l;
    float* op = O + (size_t)(b * SS + q0 + r) * DD + h * 64 + dh;
    for (int j = 0; j < 32; j++) op[j] = acc[j] * inv;
#endif
}

// ---------------- launch -------------------------------------------------------
extern "C" void kernel_launch(void* const* d_in, const int* in_sizes, int n_in,
                              void* d_out, int out_size) {
    const float* x   = (const float*)d_in[0];
    const float* wq  = (const float*)d_in[1];
    const float* wk  = (const float*)d_in[2];
    const float* wv  = (const float*)d_in[3];
    const float* wo  = (const float*)d_in[4];
    const float* w1  = (const float*)d_in[5];
    const float* b1  = (const float*)d_in[6];
    const float* w2  = (const float*)d_in[7];
    const float* b2  = (const float*)d_in[8];
    const float* g1  = (const float*)d_in[9];
    const float* be1 = (const float*)d_in[10];
    const float* g2  = (const float*)d_in[11];
    const float* be2 = (const float*)d_in[12];
    float* out = (float*)d_out;

    float *h, *qkv, *attn, *x1, *ffn, *vT;
    float *wqkvT, *woT, *w1T, *w2T;
    cudaGetSymbolAddress((void**)&h, g_h);
    cudaGetSymbolAddress((void**)&qkv, g_qkv);
    cudaGetSymbolAddress((void**)&attn, g_attn);
    cudaGetSymbolAddress((void**)&x1, g_x1);
    cudaGetSymbolAddress((void**)&ffn, g_ffn);
    cudaGetSymbolAddress((void**)&vT, g_vT);
    cudaGetSymbolAddress((void**)&wqkvT, g_wqkvT);
    cudaGetSymbolAddress((void**)&woT, g_woT);
    cudaGetSymbolAddress((void**)&w1T, g_w1T);
    cudaGetSymbolAddress((void**)&w2T, g_w2T);

    static bool attr_done = false;
    if (!attr_done) {
        cudaFuncSetAttribute(attn_tc,
                             cudaFuncAttributeMaxDynamicSharedMemorySize, ATTN_TC_SMEM);
        cudaFuncSetAttribute(gemm_tc<false, false, false, true, true>,
                             cudaFuncAttributeMaxDynamicSharedMemorySize, GT_SMEM);
        cudaFuncSetAttribute(gemm_tc<false, false, true, false, false>,
                             cudaFuncAttributeMaxDynamicSharedMemorySize, GT_SMEM);
        cudaFuncSetAttribute(gemm_tc<true, true, false, false, false>,
                             cudaFuncAttributeMaxDynamicSharedMemorySize, GT_SMEM);
        cudaFuncSetAttribute(gemm_tc<true, false, true, false, false>,
                             cudaFuncAttributeMaxDynamicSharedMemorySize, GT_SMEM);
        attr_done = true;
    }

    // weight transposes -> [N, K], tf32-rounded; qkv weights concatenated
    transpose_kernel<<<dim3(DD / 32, DD / 32), 256>>>(wq, wqkvT, DD, DD);
    transpose_kernel<<<dim3(DD / 32, DD / 32), 256>>>(wk, wqkvT + (size_t)DD * DD, DD, DD);
    transpose_kernel<<<dim3(DD / 32, DD / 32), 256>>>(wv, wqkvT + (size_t)2 * DD * DD, DD, DD);
    transpose_kernel<<<dim3(DD / 32, DD / 32), 256>>>(wo, woT, DD, DD);
    transpose_kernel<<<dim3(DFF / 32, DD / 32), 256>>>(w1, w1T, DD, DFF);
    transpose_kernel<<<dim3(DD / 32, DFF / 32), 256>>>(w2, w2T, DFF, DD);

    dim3 gQKV(3 * DD / TN, NT / 128);   // (12, 64)
    dim3 gWo(DD / TN, NT / 128);        // (4, 64)
    dim3 gF1(DFF / TN, NT / 128);       // (16, 64)
    dim3 gF2(DD / TN, NT / 128);        // (4, 64)

    ln_kernel<<<NT / 8, 256>>>(x, g1, be1, h);
    gemm_tc<false, false, false, true, true><<<gQKV, 256, GT_SMEM>>>(
        h, wqkvT, nullptr, nullptr, qkv, 3 * DD, DD);
    vt_kernel<<<dim3(SS / 32, DK / 32, BB * HH), 256>>>(qkv + 2 * DD, vT);
    attn_tc<<<dim3(SS / 128, HH, BB), 256, ATTN_TC_SMEM>>>(qkv, qkv + DD, vT, attn);
    gemm_tc<false, false, true, false, false><<<gWo, 256, GT_SMEM>>>(
        attn, woT, nullptr, x, x1, DD, DD);
    ln_kernel<<<NT / 8, 256>>>(x1, g2, be2, h);
    gemm_tc<true, true, false, false, false><<<gF1, 256, GT_SMEM>>>(
        h, w1T, b1, nullptr, ffn, DFF, DD);
    gemm_tc<true, false, true, false, false><<<gF2, 256, GT_SMEM>>>(
        ffn, w2T, b2, x1, out, DD, DFF);
}

// round 15
// speedup vs baseline: 2.3184x; 1.4250x over previous
#include <cuda_runtime.h>
#include <cuda_fp16.h>
#include <math.h>
#include <cstdint>

// Problem constants
#define BB 4
#define SS 2048
#define DD 1024
#define HH 16
#define DK 64
#define DFF 4096
#define NT (BB * SS)   // 8192 tokens
#define EPS 1e-5f
#define QSTR (3 * DD)  // row stride of fused qkv buffer (halves)

// Does this compilation pass have sm_103a-specific (tcgen05) features?
#if !defined(__CUDA_ARCH__) || defined(__CUDA_ARCH_FEAT_SM103_ALL) || \
    defined(__CUDA_ARCH_FEAT_SM100_ALL) || defined(__CUDA_ARCH_SPECIFIC__)
#define HAS_TCGEN05 1
#else
#define HAS_TCGEN05 0
#endif

// ---------------- scratch (device globals; no allocs allowed) ----------------
__device__ __half g_h[(size_t)NT * DD];
__device__ __half g_qkv[(size_t)NT * 3 * DD];   // fused q|k|v, row stride 3072
__device__ __half g_attn[(size_t)NT * DD];
__device__ float  g_x1[(size_t)NT * DD];
__device__ __half g_ffn[(size_t)NT * DFF];
__device__ __half g_vT[(size_t)BB * HH * DK * SS];   // [b,h,dk,s]
// transposed weights [N, K] (fp16); wqkvT = concat(wqT, wkT, wvT)
__device__ __half g_wqkvT[(size_t)3 * DD * DD];
__device__ __half g_woT[(size_t)DD * DD];
__device__ __half g_w1T[(size_t)DFF * DD];
__device__ __half g_w2T[(size_t)DD * DFF];

// ---------------- PTX helpers --------------------------------------------------
__device__ __forceinline__ uint32_t smem_u32(const void* p) {
    uint32_t a;
    asm("{ .reg .u64 t; cvta.to.shared.u64 t, %1; cvt.u32.u64 %0, t; }"
        : "=r"(a) : "l"(p));
    return a;
}
__device__ __forceinline__ uint32_t elect_one() {
    uint32_t p;
    asm volatile("{ .reg .pred p; elect.sync _|p, 0xFFFFFFFF; selp.b32 %0,1,0,p; }"
                 : "=r"(p));
    return p;
}
#define MBAR_INIT(a, c) \
    asm volatile("mbarrier.init.shared.b64 [%0], %1;" :: "r"((uint32_t)(a)), "r"((uint32_t)(c)) : "memory")
#define MBAR_WAIT(a, par) do {                                                   \
    uint32_t _m = (uint32_t)(a); uint32_t _p = (uint32_t)(par); uint32_t _d;     \
    asm volatile("{ .reg .pred p; mbarrier.try_wait.parity.acquire.cta.shared::cta.b64 p, [%1], %2;" \
                 " selp.b32 %0,1,0,p; }" : "=r"(_d) : "r"(_m), "r"(_p) : "memory"); \
    if (!_d) {                                                                   \
        asm volatile("{ .reg .pred P1; WL_%=: mbarrier.try_wait.parity.acquire.cta.shared::cta.b64 P1, [%0], %1, 0x989680;" \
                     " @P1 bra.uni WD_%=; bra.uni WL_%=; WD_%=: }"               \
                     :: "r"(_m), "r"(_p) : "memory");                            \
    } } while (0)
#define CP16(dst, src) \
    asm volatile("cp.async.cg.shared.global [%0], [%1], 16;" \
                 :: "r"((uint32_t)(dst)), "l"(src) : "memory")
#define CP_COMMIT() asm volatile("cp.async.commit_group;" ::: "memory")
#define CP_WAIT1()  asm volatile("cp.async.wait_group 1;" ::: "memory")
#define CP_WAIT0()  asm volatile("cp.async.wait_group 0;" ::: "memory")
#define FENCE_ASYNC() asm volatile("fence.proxy.async.shared::cta;" ::: "memory")

#if HAS_TCGEN05
#define TC_ALLOC(smem_addr, n) \
    asm volatile("tcgen05.alloc.cta_group::1.sync.aligned.shared::cta.b32 [%0], %1;" \
                 :: "r"((uint32_t)(smem_addr)), "r"((uint32_t)(n)) : "memory")
#define TC_DEALLOC(tmem, n) \
    asm volatile("tcgen05.dealloc.cta_group::1.sync.aligned.b32 %0, %1;" \
                 :: "r"(tmem), "r"((uint32_t)(n)))
#define TC_RELINQ() \
    asm volatile("tcgen05.relinquish_alloc_permit.cta_group::1.sync.aligned;")
#define TC_COMMIT(mbar) \
    asm volatile("tcgen05.commit.cta_group::1.mbarrier::arrive::one.shared::cluster.b64 [%0];" \
                 :: "r"((uint32_t)(mbar)) : "memory")
#define TC_WAIT_LD() asm volatile("tcgen05.wait::ld.sync.aligned;" ::: "memory")
#define TC_FENCE_BEFORE() asm volatile("tcgen05.fence::before_thread_sync;" ::: "memory")
#define TC_FENCE_AFTER()  asm volatile("tcgen05.fence::after_thread_sync;" ::: "memory")
#define TC_LD_X32(r, tmem)                                                        \
    asm volatile("tcgen05.ld.sync.aligned.32x32b.x32.b32 "                        \
        "{%0,%1,%2,%3,%4,%5,%6,%7,%8,%9,%10,%11,%12,%13,%14,%15,"                 \
        "%16,%17,%18,%19,%20,%21,%22,%23,%24,%25,%26,%27,%28,%29,%30,%31}, [%32];"\
        : "=r"((r)[0]),"=r"((r)[1]),"=r"((r)[2]),"=r"((r)[3]),                    \
          "=r"((r)[4]),"=r"((r)[5]),"=r"((r)[6]),"=r"((r)[7]),                    \
          "=r"((r)[8]),"=r"((r)[9]),"=r"((r)[10]),"=r"((r)[11]),                  \
          "=r"((r)[12]),"=r"((r)[13]),"=r"((r)[14]),"=r"((r)[15]),                \
          "=r"((r)[16]),"=r"((r)[17]),"=r"((r)[18]),"=r"((r)[19]),                \
          "=r"((r)[20]),"=r"((r)[21]),"=r"((r)[22]),"=r"((r)[23]),                \
          "=r"((r)[24]),"=r"((r)[25]),"=r"((r)[26]),"=r"((r)[27]),                \
          "=r"((r)[28]),"=r"((r)[29]),"=r"((r)[30]),"=r"((r)[31])                 \
        : "r"(tmem))

static constexpr uint64_t DESC_SW128 =
    (uint64_t(2) << 61) | (uint64_t(1) << 46) | (uint64_t(64) << 32) | (uint64_t(1) << 16);
__device__ __forceinline__ uint64_t make_desc(uint32_t addr) {
    return DESC_SW128 | ((uint64_t)(addr >> 4) & 0x3FFF);
}
// f16 idesc: c=F32(1<<4), atype=btype=F16(0), N<<17/8, M<<24/16
#define IDESC_F16_N256 0x8400010u
#define IDESC_F16_N128 0x8200010u
#define IDESC_F16_N64  0x8100010u
__device__ __forceinline__ void mma_f16_ss(uint32_t d, uint64_t ad, uint64_t bd,
                                           uint32_t idesc, uint32_t en) {
    uint32_t zero = 0;
    asm volatile("{ .reg .pred p; setp.ne.u32 p, %6, 0;"
                 " tcgen05.mma.cta_group::1.kind::f16 [%0], %1, %2, %3, "
                 "{%4, %4, %4, %4}, p; }"
                 :: "r"(d), "l"(ad), "l"(bd), "r"(idesc),
                    "r"(zero), "r"(zero), "r"(en) : "memory");
}
#endif  // HAS_TCGEN05

// ---------------- weight transpose: out[C][R] = half(in[R][C]) ----------------
__global__ __launch_bounds__(256) void transpose_kernel(const float* __restrict__ in,
                                                        __half* __restrict__ out,
                                                        int R, int C) {
    __shared__ float t[32][33];
    int tx = threadIdx.x & 31, ty = threadIdx.x >> 5;  // 32 x 8
    int c0 = blockIdx.x * 32, r0 = blockIdx.y * 32;
#pragma unroll
    for (int i = 0; i < 4; i++)
        t[ty + 8 * i][tx] = in[(size_t)(r0 + ty + 8 * i) * C + c0 + tx];
    __syncthreads();
#pragma unroll
    for (int i = 0; i < 4; i++)
        out[(size_t)(c0 + ty + 8 * i) * R + r0 + tx] = __float2half_rn(t[tx][ty + 8 * i]);
}

// ---------------- v transpose (from fused qkv, half) -> vT[b,h,dk,s] ----------
__global__ __launch_bounds__(256) void vt_kernel(const __half* __restrict__ vsec,
                                                 __half* __restrict__ vT) {
    __shared__ __half t[32][33];
    int tx = threadIdx.x & 31, ty = threadIdx.x >> 5;
    int bh = blockIdx.z;
    int b = bh >> 4, h = bh & 15;
    int s0 = blockIdx.x * 32, d0 = blockIdx.y * 32;
#pragma unroll
    for (int i = 0; i < 4; i++)
        t[ty + 8 * i][tx] =
            vsec[(size_t)(b * SS + s0 + ty + 8 * i) * QSTR + h * 64 + d0 + tx];
    __syncthreads();
#pragma unroll
    for (int i = 0; i < 4; i++)
        vT[((size_t)bh * DK + d0 + ty + 8 * i) * SS + s0 + tx] = t[tx][ty + 8 * i];
}

// ---------------- LayerNorm: 1 warp per row, fp32 in, fp16 out ----------------
__global__ __launch_bounds__(256) void ln_kernel(const float* __restrict__ x,
                                                 const float* __restrict__ g,
                                                 const float* __restrict__ b,
                                                 __half* __restrict__ out) {
    int w = threadIdx.x >> 5, lane = threadIdx.x & 31;
    int row = blockIdx.x * 8 + w;
    const float4* xr = reinterpret_cast<const float4*>(x + (size_t)row * DD);
    float4 v[8];
    float s = 0.f;
#pragma unroll
    for (int i = 0; i < 8; i++) {
        v[i] = xr[lane + 32 * i];
        s += v[i].x + v[i].y + v[i].z + v[i].w;
    }
#pragma unroll
    for (int o = 16; o > 0; o >>= 1) s += __shfl_xor_sync(~0u, s, o);
    float mu = s * (1.f / DD);
    float s2 = 0.f;
#pragma unroll
    for (int i = 0; i < 8; i++) {
        float dx = v[i].x - mu, dy = v[i].y - mu, dz = v[i].z - mu, dw = v[i].w - mu;
        s2 += dx * dx + dy * dy + dz * dz + dw * dw;
    }
#pragma unroll
    for (int o = 16; o > 0; o >>= 1) s2 += __shfl_xor_sync(~0u, s2, o);
    float rstd = rsqrtf(s2 * (1.f / DD) + EPS);
    const float4* gp = reinterpret_cast<const float4*>(g);
    const float4* bp = reinterpret_cast<const float4*>(b);
    uint2* op = reinterpret_cast<uint2*>(out + (size_t)row * DD);
#pragma unroll
    for (int i = 0; i < 8; i++) {
        float4 gg = gp[lane + 32 * i], bb = bp[lane + 32 * i];
        __half2 lo = __floats2half2_rn((v[i].x - mu) * rstd * gg.x + bb.x,
                                       (v[i].y - mu) * rstd * gg.y + bb.y);
        __half2 hi = __floats2half2_rn((v[i].z - mu) * rstd * gg.z + bb.z,
                                       (v[i].w - mu) * rstd * gg.w + bb.w);
        uint2 u;
        u.x = *reinterpret_cast<uint32_t*>(&lo);
        u.y = *reinterpret_cast<uint32_t*>(&hi);
        op[lane + 32 * i] = u;
    }
}

// ---------------- GEMM: C[M,N] = A[M,K] @ BT[N,K]^T (fp16 operands) -----------
// Tile 128 x 256, 2-stage cp.async pipeline, K-chunk 64 (128B rows);
// stage = 16KB A + 32KB B = 48KB; 99328 B smem -> 2 CTAs/SM.
// HALFOUT: store __half(v); QKVSCALE: cm = 0.125 for cols < DD (q section).
#define TN 256
#define NST 2
#define STAGE (16384 + 32768)
#define GT_SMEM (1024 + NST * STAGE)   // 99328

template <bool BIAS, bool RELU, bool RES, bool HALFOUT, bool QKVSCALE>
__global__ __launch_bounds__(256)
void gemm_tc(const __half* __restrict__ A, const __half* __restrict__ BT,
             const float* __restrict__ bias, const float* __restrict__ res,
             void* __restrict__ Cv, int N, int K) {
#if HAS_TCGEN05
    extern __shared__ char smem[];
    uint32_t sb = smem_u32(smem);
    int tid = threadIdx.x;
    int wid = tid >> 5, lid = tid & 31;
    int bm0 = blockIdx.y * 128, bn0 = blockIdx.x * TN;

    if (wid == 0) {
        TC_ALLOC(sb, TN);
        TC_RELINQ();
    }
    if (tid == 0) { MBAR_INIT(sb + 8, 1); MBAR_INIT(sb + 16, 1); }
    __syncthreads();
    uint32_t tmem;
    asm volatile("ld.shared.b32 %0, [%1];" : "=r"(tmem) : "r"(sb));

    const int nc = K >> 6;   // K-chunks of 64 halves (128 bytes)

    auto issue_stage = [&](int t) {
        int s = t % NST;
        uint32_t ab = sb + 1024 + s * STAGE;
        const __half* Ag = A + (size_t)bm0 * K + t * 64;
        const __half* Bg = BT + (size_t)bn0 * K + t * 64;
#pragma unroll
        for (int i = 0; i < 4; i++) {           // A: 128 rows x 8 segs
            int idx = tid + 256 * i;
            int r = idx >> 3, f = idx & 7;
            uint32_t off = (uint32_t)(r * 128 + f * 16);
            off ^= (off >> 3) & 0x70;
            CP16(ab + off, Ag + (size_t)r * K + f * 8);
        }
#pragma unroll
        for (int i = 0; i < 8; i++) {           // B: 256 rows x 8 segs
            int idx = tid + 256 * i;
            int r = idx >> 3, f = idx & 7;
            uint32_t off = (uint32_t)(r * 128 + f * 16);
            off ^= (off >> 3) & 0x70;
            CP16(ab + 16384 + off, Bg + (size_t)r * K + f * 8);
        }
        CP_COMMIT();
    };

    issue_stage(0);
    issue_stage(1);

    for (int t = 0; t < nc; t++) {
        if (t < nc - NST) { CP_WAIT1(); } else { CP_WAIT0(); }
        FENCE_ASYNC();
        __syncthreads();
        if (wid == 0 && elect_one()) {
            uint32_t base = sb + 1024 + (t % NST) * STAGE;
            uint64_t ad = make_desc(base);
            uint64_t bd = make_desc(base + 16384);
#pragma unroll
            for (int k = 0; k < 4; k++)   // K=16 per MMA, 4 per chunk
                mma_f16_ss(tmem, ad + k * 2, bd + k * 2, IDESC_F16_N256,
                           (t > 0 || k > 0) ? 1u : 0u);
            TC_COMMIT(sb + 8 + 8 * (t % NST));
        }
        if (t + NST < nc) {
            MBAR_WAIT(sb + 8 + 8 * (t % NST), (t / NST) & 1);
            issue_stage(t + NST);
        }
    }
    for (int tt = nc - NST; tt < nc; tt++)
        MBAR_WAIT(sb + 8 + 8 * (tt % NST), (tt / NST) & 1);
    TC_FENCE_AFTER();
    __syncthreads();

    // epilogue: warps 0-3 read TMEM, transpose via smem, store coalesced
    float cm = 1.f;
    if (QKVSCALE) cm = (bn0 < DD) ? 0.125f : 1.f;
    if (tid < 128) {
        float* tw = reinterpret_cast<float*>(smem + 1024) + wid * (32 * 33 + 8);
#pragma unroll
        for (int cb = 0; cb < TN; cb += 32) {
            uint32_t regs[32];
            TC_LD_X32(regs, tmem + cb);
            TC_WAIT_LD();
#pragma unroll
            for (int j = 0; j < 32; j++) tw[lid * 33 + j] = __uint_as_float(regs[j]);
            __syncwarp();
            float bv = BIAS ? bias[bn0 + cb + lid] : 0.f;
#pragma unroll 4
            for (int r = 0; r < 32; r++) {
                int row = bm0 + wid * 32 + r;
                int col = bn0 + cb + lid;
                float v = tw[r * 33 + lid];
                if (QKVSCALE) v *= cm;
                if (BIAS) v += bv;
                if (RELU) v = fmaxf(v, 0.f);
                if (HALFOUT) {
                    reinterpret_cast<__half*>(Cv)[(size_t)row * N + col] =
                        __float2half_rn(v);
                } else {
                    if (RES) v += res[(size_t)row * N + col];
                    reinterpret_cast<float*>(Cv)[(size_t)row * N + col] = v;
                }
            }
            __syncwarp();
        }
    }
    TC_FENCE_BEFORE();
    __syncthreads();
    if (wid == 0) TC_DEALLOC(tmem, TN);
#else
    // SIMT fallback (plain sm_103 pass; not expected to be selected)
    extern __shared__ char smem[];
    float* As = reinterpret_cast<float*>(smem);          // [16][128]
    float* Bs = As + 16 * 128;
    int tid = threadIdx.x;
    int bm0 = blockIdx.y * 128;
    int tx = tid & 15, ty = tid >> 4;
    for (int nh = 0; nh < TN / 128; nh++) {
        int bn0 = blockIdx.x * TN + nh * 128;
        float cm = 1.f;
        if (QKVSCALE) cm = (bn0 < DD) ? 0.125f : 1.f;
        float acc[8][8];
#pragma unroll
        for (int i = 0; i < 8; i++)
#pragma unroll
            for (int j = 0; j < 8; j++) acc[i][j] = 0.f;
        for (int kt = 0; kt < K; kt += 16) {
            __syncthreads();
            for (int idx = tid; idx < 128 * 16; idx += 256) {
                int r = idx >> 4, c = idx & 15;
                As[c * 128 + r] = __half2float(A[(size_t)(bm0 + r) * K + kt + c]);
                Bs[c * 128 + r] = __half2float(BT[(size_t)(bn0 + r) * K + kt + c]);
            }
            __syncthreads();
#pragma unroll
            for (int k = 0; k < 16; k++) {
                float a[8], bb[8];
#pragma unroll
                for (int i = 0; i < 4; i++) {
                    a[i] = As[k * 128 + ty * 4 + i];
                    a[i + 4] = As[k * 128 + 64 + ty * 4 + i];
                    bb[i] = Bs[k * 128 + tx * 4 + i];
                    bb[i + 4] = Bs[k * 128 + 64 + tx * 4 + i];
                }
#pragma unroll
                for (int i = 0; i < 8; i++)
#pragma unroll
                    for (int j = 0; j < 8; j++) acc[i][j] = fmaf(a[i], bb[j], acc[i][j]);
            }
        }
#pragma unroll
        for (int i = 0; i < 8; i++) {
            int row = bm0 + ((i < 4) ? (ty * 4 + i) : (64 + ty * 4 + i - 4));
#pragma unroll
            for (int j = 0; j < 8; j++) {
                int col = bn0 + ((j < 4) ? (tx * 4 + j) : (64 + tx * 4 + j - 4));
                float v = acc[i][j];
                if (QKVSCALE) v *= cm;
                if (BIAS) v += bias[col];
                if (RELU) v = fmaxf(v, 0.f);
                if (HALFOUT) {
                    reinterpret_cast<__half*>(Cv)[(size_t)row * N + col] =
                        __float2half_rn(v);
                } else {
                    if (RES) v += res[(size_t)row * N + col];
                    reinterpret_cast<float*>(Cv)[(size_t)row * N + col] = v;
                }
            }
        }
        __syncthreads();
    }
#endif
}

// ---------------- tcgen05 attention (fp16 operands, S double-buffered) --------
// grid (S/128, H, B), 256 threads. TMEM: S0@0, S1@128, O@256 (alloc 512).
// smem: misc@0 (rs@1024), Q@2048 (16KB), K@18432+buf*16KB, V@51200+buf*16KB,
// P@83968 (32KB). Epilogue float staging at AT_OB spills 2KB into the dead P
// region (PV(15) already consumed P) — within the 116736 allocation.
#define AT_Q 2048u
#define AT_K(buf) (18432u + (buf) * 16384u)
#define AT_V(buf) (51200u + (buf) * 16384u)
#define AT_P 83968u
#define AT_OB 51200u
#define ATTN_TC_SMEM 116736

__global__ __launch_bounds__(256)
void attn_tc(const __half* __restrict__ Q, const __half* __restrict__ K,
             const __half* __restrict__ vT, __half* __restrict__ O) {
#if HAS_TCGEN05
    extern __shared__ char smem[];
    uint32_t sb = smem_u32(smem);
    int tid = threadIdx.x;
    int wid = tid >> 5, lane = tid & 31;
    int b = blockIdx.z, h = blockIdx.y;
    int q0 = blockIdx.x * 128;

    if (wid == 0) {
        TC_ALLOC(sb, 512);
        TC_RELINQ();
    }
    if (tid == 0) { MBAR_INIT(sb + 8, 1); MBAR_INIT(sb + 16, 1); }
    __syncthreads();
    uint32_t tmem;
    asm volatile("ld.shared.b32 %0, [%1];" : "=r"(tmem) : "r"(sb));
    uint32_t tmem_O = tmem + 256;

    auto issue_kv = [&](int t) {
        int buf = t & 1;
        const __half* Kp = K + (size_t)(b * SS + t * 128) * QSTR + h * 64;
#pragma unroll
        for (int i = 0; i < 4; i++) {           // K: 128 rows x 8 segs (16KB)
            int idx = tid + 256 * i;
            int r = idx >> 3, f = idx & 7;
            uint32_t byte = (uint32_t)(r * 128 + f * 16);
            byte ^= (byte >> 3) & 0x70;
            CP16(sb + AT_K(buf) + byte, Kp + (size_t)r * QSTR + f * 8);
        }
        const __half* Vp = vT + ((size_t)(b * HH + h) * DK) * SS + t * 128;
#pragma unroll
        for (int i = 0; i < 4; i++) {           // V: 64 rows x 16 segs (16KB)
            int idx = tid + 256 * i;
            int d = idx >> 4, f = idx & 15;
            uint32_t byte = (uint32_t)(((d >> 3) + (f >> 3) * 8) * 1024 +
                                       (d & 7) * 128 + (f & 7) * 16);
            byte ^= (byte >> 3) & 0x70;
            CP16(sb + AT_V(buf) + byte, Vp + (size_t)d * SS + f * 8);
        }
        CP_COMMIT();
    };

    uint64_t descQ = make_desc(sb + AT_Q);

    auto s_mma = [&](int t) {   // S(t) = Q @ K(t)^T, K=64: 4 dispatches
        uint64_t descK = make_desc(sb + AT_K(t & 1));
        uint32_t dst = tmem + (t & 1) * 128;
#pragma unroll
        for (int k = 0; k < 4; k++)
            mma_f16_ss(dst, descQ + k * 2, descK + k * 2,
                       IDESC_F16_N128, k > 0 ? 1u : 0u);
        TC_COMMIT(sb + 8);
    };

    // prologue: Q + kv(0); wait; S(0); prefetch kv(1)
    {
        const __half* Qp = Q + (size_t)(b * SS + q0) * QSTR + h * 64;
#pragma unroll
        for (int i = 0; i < 4; i++) {
            int idx = tid + 256 * i;
            int r = idx >> 3, f = idx & 7;
            uint32_t byte = (uint32_t)(r * 128 + f * 16);
            byte ^= (byte >> 3) & 0x70;
            CP16(sb + AT_Q + byte, Qp + (size_t)r * QSTR + f * 8);
        }
        issue_kv(0);
        CP_WAIT0();
        FENCE_ASYNC();
        __syncthreads();
        if (wid == 0 && elect_one()) s_mma(0);
        issue_kv(1);
    }

    float rsum = 0.f;
    const int sp = wid & 3;
    const int srow = sp * 32 + lane;
    const int colbase = (wid >> 2) * 64;

    for (int t = 0; t < 16; t++) {
        MBAR_WAIT(sb + 8, t & 1);     // S(t) done (implies PV(t-1) done too)
        TC_FENCE_AFTER();

        // softmax(t): warp w handles cols [colbase, colbase+64); P stored fp16
        uint32_t tS = tmem + (t & 1) * 128;
#pragma unroll
        for (int cb2 = 0; cb2 < 64; cb2 += 32) {
            uint32_t regs[32];
            TC_LD_X32(regs, tS + colbase + cb2);
            TC_WAIT_LD();
            float e[32];
#pragma unroll
            for (int j = 0; j < 32; j++) {
                e[j] = __expf(__uint_as_float(regs[j]));
                rsum += e[j];
            }
#pragma unroll
            for (int j0 = 0; j0 < 32; j0 += 8) {
                uint4 u;
                __half2 h0 = __floats2half2_rn(e[j0 + 0], e[j0 + 1]);
                __half2 h1 = __floats2half2_rn(e[j0 + 2], e[j0 + 3]);
                __half2 h2 = __floats2half2_rn(e[j0 + 4], e[j0 + 5]);
                __half2 h3 = __floats2half2_rn(e[j0 + 6], e[j0 + 7]);
                u.x = *reinterpret_cast<uint32_t*>(&h0);
                u.y = *reinterpret_cast<uint32_t*>(&h1);
                u.z = *reinterpret_cast<uint32_t*>(&h2);
                u.w = *reinterpret_cast<uint32_t*>(&h3);
                int c = colbase + cb2 + j0;
                int cbyte = 2 * c;
                uint32_t byte = (uint32_t)(((srow >> 3) + (cbyte >> 7) * 16) * 1024 +
                                           (srow & 7) * 128 + (cbyte & 127));
                byte ^= (byte >> 3) & 0x70;
                *reinterpret_cast<uint4*>(smem + AT_P + byte) = u;
            }
        }
        CP_WAIT0();       // kv(t+1) resident (no-op at t=15)
        FENCE_ASYNC();
        __syncthreads();  // P ready + kv(t+1) visible

        if (wid == 0 && elect_one()) {
            // PV(t): O += P @ V(t)^T, K=128: 8 dispatches
            uint64_t descP = make_desc(sb + AT_P);
            uint64_t descV = make_desc(sb + AT_V(t & 1));
#pragma unroll
            for (int k = 0; k < 8; k++)
                mma_f16_ss(tmem_O,
                           descP + (k >> 2) * 1024 + (k & 3) * 2,
                           descV + (k >> 2) * 512 + (k & 3) * 2,
                           IDESC_F16_N64, (t > 0 || k > 0) ? 1u : 0u);
            TC_COMMIT(sb + 16);
            if (t < 15) s_mma(t + 1);   // S(t+1) queued behind PV(t)
        }
        if (t < 15) {
            MBAR_WAIT(sb + 16, t & 1);  // PV(t) done: buf t&1 free
            if (t + 2 < 16) issue_kv(t + 2);
        }
    }
    MBAR_WAIT(sb + 16, 15 & 1);
    TC_FENCE_AFTER();

    // combine per-warp rsum partials (warps w and w+4 share rows)
    float* rs = reinterpret_cast<float*>(smem + 1024);
    rs[wid * 32 + lane] = rsum;
    __syncthreads();

    // epilogue: normalize O, stage as float, store fp16
    float* ob = reinterpret_cast<float*>(smem + AT_OB);
    if (wid < 4) {
        float inv = 1.f / (rs[wid * 32 + lane] + rs[(wid + 4) * 32 + lane]);
        uint32_t r0[32], r1[32];
        TC_LD_X32(r0, tmem_O);
        TC_LD_X32(r1, tmem_O + 32);
        TC_WAIT_LD();
#pragma unroll
        for (int j = 0; j < 32; j++) {
            ob[srow * 68 + j] = __uint_as_float(r0[j]) * inv;
            ob[srow * 68 + 32 + j] = __uint_as_float(r1[j]) * inv;
        }
    }
    TC_FENCE_BEFORE();
    __syncthreads();
#pragma unroll
    for (int p = 0; p < 8; p++) {
        int slot = tid + 256 * p;
        int r = slot >> 4, f = slot & 15;
        __half2 lo = __floats2half2_rn(ob[r * 68 + f * 4 + 0], ob[r * 68 + f * 4 + 1]);
        __half2 hi = __floats2half2_rn(ob[r * 68 + f * 4 + 2], ob[r * 68 + f * 4 + 3]);
        uint2 u;
        u.x = *reinterpret_cast<uint32_t*>(&lo);
        u.y = *reinterpret_cast<uint32_t*>(&hi);
        *reinterpret_cast<uint2*>(O + (size_t)(b * SS + q0 + r) * DD + h * 64 + f * 4) = u;
    }
    __syncthreads();
    if (wid == 0) TC_DEALLOC(tmem, 512);
#else
    // naive SIMT fallback (q pre-scaled by 1/8; qkv strided, half)
    int tid = threadIdx.x;
    int b = blockIdx.z, h = blockIdx.y;
    int q0 = blockIdx.x * 128;
    int r = tid >> 1, dh = (tid & 1) * 32;
    const __half* qp = Q + (size_t)(b * SS + q0 + r) * QSTR + h * 64;
    float acc[32];
#pragma unroll
    for (int j = 0; j < 32; j++) acc[j] = 0.f;
    float l = 0.f;
    for (int kv = 0; kv < SS; kv++) {
        const __half* kp = K + (size_t)(b * SS + kv) * QSTR + h * 64;
        float s = 0.f;
        for (int d = 0; d < 64; d++) s += __half2float(qp[d]) * __half2float(kp[d]);
        float e = __expf(s);
        l += e;
        const __half* vp = vT + ((size_t)(b * HH + h) * DK + dh) * SS + kv;
        for (int j = 0; j < 32; j++) acc[j] += e * __half2float(vp[(size_t)j * SS]);
    }
    float inv = 1.f / l;
    __half* op = O + (size_t)(b * SS + q0 + r) * DD + h * 64 + dh;
    for (int j = 0; j < 32; j++) op[j] = __float2half_rn(acc[j] * inv);
#endif
}

// ---------------- launch -------------------------------------------------------
extern "C" void kernel_launch(void* const* d_in, const int* in_sizes, int n_in,
                              void* d_out, int out_size) {
    const float* x   = (const float*)d_in[0];
    const float* wq  = (const float*)d_in[1];
    const float* wk  = (const float*)d_in[2];
    const float* wv  = (const float*)d_in[3];
    const float* wo  = (const float*)d_in[4];
    const float* w1  = (const float*)d_in[5];
    const float* b1  = (const float*)d_in[6];
    const float* w2  = (const float*)d_in[7];
    const float* b2  = (const float*)d_in[8];
    const float* g1  = (const float*)d_in[9];
    const float* be1 = (const float*)d_in[10];
    const float* g2  = (const float*)d_in[11];
    const float* be2 = (const float*)d_in[12];
    float* out = (float*)d_out;

    __half *h, *qkv, *attn, *ffn, *vT, *wqkvT, *woT, *w1T, *w2T;
    float *x1;
    cudaGetSymbolAddress((void**)&h, g_h);
    cudaGetSymbolAddress((void**)&qkv, g_qkv);
    cudaGetSymbolAddress((void**)&attn, g_attn);
    cudaGetSymbolAddress((void**)&x1, g_x1);
    cudaGetSymbolAddress((void**)&ffn, g_ffn);
    cudaGetSymbolAddress((void**)&vT, g_vT);
    cudaGetSymbolAddress((void**)&wqkvT, g_wqkvT);
    cudaGetSymbolAddress((void**)&woT, g_woT);
    cudaGetSymbolAddress((void**)&w1T, g_w1T);
    cudaGetSymbolAddress((void**)&w2T, g_w2T);

    static bool attr_done = false;
    if (!attr_done) {
        cudaFuncSetAttribute(attn_tc,
                             cudaFuncAttributeMaxDynamicSharedMemorySize, ATTN_TC_SMEM);
        cudaFuncSetAttribute(gemm_tc<false, false, false, true, true>,
                             cudaFuncAttributeMaxDynamicSharedMemorySize, GT_SMEM);
        cudaFuncSetAttribute(gemm_tc<false, false, true, false, false>,
                             cudaFuncAttributeMaxDynamicSharedMemorySize, GT_SMEM);
        cudaFuncSetAttribute(gemm_tc<true, true, false, true, false>,
                             cudaFuncAttributeMaxDynamicSharedMemorySize, GT_SMEM);
        cudaFuncSetAttribute(gemm_tc<true, false, true, false, false>,
                             cudaFuncAttributeMaxDynamicSharedMemorySize, GT_SMEM);
        attr_done = true;
    }

    // weight transposes -> [N, K], fp16; qkv weights concatenated
    transpose_kernel<<<dim3(DD / 32, DD / 32), 256>>>(wq, wqkvT, DD, DD);
    transpose_kernel<<<dim3(DD / 32, DD / 32), 256>>>(wk, wqkvT + (size_t)DD * DD, DD, DD);
    transpose_kernel<<<dim3(DD / 32, DD / 32), 256>>>(wv, wqkvT + (size_t)2 * DD * DD, DD, DD);
    transpose_kernel<<<dim3(DD / 32, DD / 32), 256>>>(wo, woT, DD, DD);
    transpose_kernel<<<dim3(DFF / 32, DD / 32), 256>>>(w1, w1T, DD, DFF);
    transpose_kernel<<<dim3(DD / 32, DFF / 32), 256>>>(w2, w2T, DFF, DD);

    dim3 gQKV(3 * DD / TN, NT / 128);   // (12, 64)
    dim3 gWo(DD / TN, NT / 128);        // (4, 64)
    dim3 gF1(DFF / TN, NT / 128);       // (16, 64)
    dim3 gF2(DD / TN, NT / 128);        // (4, 64)

    ln_kernel<<<NT / 8, 256>>>(x, g1, be1, h);
    gemm_tc<false, false, false, true, true><<<gQKV, 256, GT_SMEM>>>(
        h, wqkvT, nullptr, nullptr, qkv, 3 * DD, DD);
    vt_kernel<<<dim3(SS / 32, DK / 32, BB * HH), 256>>>(qkv + 2 * DD, vT);
    attn_tc<<<dim3(SS / 128, HH, BB), 256, ATTN_TC_SMEM>>>(qkv, qkv + DD, vT, attn);
    gemm_tc<false, false, true, false, false><<<gWo, 256, GT_SMEM>>>(
        attn, woT, nullptr, x, x1, DD, DD);
    ln_kernel<<<NT / 8, 256>>>(x1, g2, be2, h);
    gemm_tc<true, true, false, true, false><<<gF1, 256, GT_SMEM>>>(
        h, w1T, b1, nullptr, ffn, DFF, DD);
    gemm_tc<true, false, true, false, false><<<gF2, 256, GT_SMEM>>>(
        ffn, w2T, b2, x1, out, DD, DFF);
}

// round 16
// speedup vs baseline: 2.4514x; 1.0573x over previous
#include <cuda_runtime.h>
#include <cuda_fp16.h>
#include <math.h>
#include <cstdint>

// Problem constants
#define BB 4
#define SS 2048
#define DD 1024
#define HH 16
#define DK 64
#define DFF 4096
#define NT (BB * SS)   // 8192 tokens
#define EPS 1e-5f
#define QSTR (3 * DD)  // row stride of fused qkv buffer (halves)

// Does this compilation pass have sm_103a-specific (tcgen05) features?
#if !defined(__CUDA_ARCH__) || defined(__CUDA_ARCH_FEAT_SM103_ALL) || \
    defined(__CUDA_ARCH_FEAT_SM100_ALL) || defined(__CUDA_ARCH_SPECIFIC__)
#define HAS_TCGEN05 1
#else
#define HAS_TCGEN05 0
#endif

// ---------------- scratch (device globals; no allocs allowed) ----------------
__device__ __half g_h[(size_t)NT * DD];
__device__ __half g_qkv[(size_t)NT * 3 * DD];   // fused q|k|v, row stride 3072
__device__ __half g_attn[(size_t)NT * DD];
__device__ float  g_x1[(size_t)NT * DD];
__device__ __half g_ffn[(size_t)NT * DFF];
__device__ __half g_vT[(size_t)BB * HH * DK * SS];   // [b,h,dk,s]
// transposed weights [N, K] (fp16); wqkvT = concat(wqT, wkT, wvT)
__device__ __half g_wqkvT[(size_t)3 * DD * DD];
__device__ __half g_woT[(size_t)DD * DD];
__device__ __half g_w1T[(size_t)DFF * DD];
__device__ __half g_w2T[(size_t)DD * DFF];

// ---------------- PTX helpers --------------------------------------------------
__device__ __forceinline__ uint32_t smem_u32(const void* p) {
    uint32_t a;
    asm("{ .reg .u64 t; cvta.to.shared.u64 t, %1; cvt.u32.u64 %0, t; }"
        : "=r"(a) : "l"(p));
    return a;
}
__device__ __forceinline__ uint32_t elect_one() {
    uint32_t p;
    asm volatile("{ .reg .pred p; elect.sync _|p, 0xFFFFFFFF; selp.b32 %0,1,0,p; }"
                 : "=r"(p));
    return p;
}
#define MBAR_INIT(a, c) \
    asm volatile("mbarrier.init.shared.b64 [%0], %1;" :: "r"((uint32_t)(a)), "r"((uint32_t)(c)) : "memory")
#define MBAR_WAIT(a, par) do {                                                   \
    uint32_t _m = (uint32_t)(a); uint32_t _p = (uint32_t)(par); uint32_t _d;     \
    asm volatile("{ .reg .pred p; mbarrier.try_wait.parity.acquire.cta.shared::cta.b64 p, [%1], %2;" \
                 " selp.b32 %0,1,0,p; }" : "=r"(_d) : "r"(_m), "r"(_p) : "memory"); \
    if (!_d) {                                                                   \
        asm volatile("{ .reg .pred P1; WL_%=: mbarrier.try_wait.parity.acquire.cta.shared::cta.b64 P1, [%0], %1, 0x989680;" \
                     " @P1 bra.uni WD_%=; bra.uni WL_%=; WD_%=: }"               \
                     :: "r"(_m), "r"(_p) : "memory");                            \
    } } while (0)
#define CP16(dst, src) \
    asm volatile("cp.async.cg.shared.global [%0], [%1], 16;" \
                 :: "r"((uint32_t)(dst)), "l"(src) : "memory")
#define CP_COMMIT() asm volatile("cp.async.commit_group;" ::: "memory")
#define CP_WAIT1()  asm volatile("cp.async.wait_group 1;" ::: "memory")
#define CP_WAIT0()  asm volatile("cp.async.wait_group 0;" ::: "memory")
#define FENCE_ASYNC() asm volatile("fence.proxy.async.shared::cta;" ::: "memory")

#if HAS_TCGEN05
#define TC_ALLOC(smem_addr, n) \
    asm volatile("tcgen05.alloc.cta_group::1.sync.aligned.shared::cta.b32 [%0], %1;" \
                 :: "r"((uint32_t)(smem_addr)), "r"((uint32_t)(n)) : "memory")
#define TC_DEALLOC(tmem, n) \
    asm volatile("tcgen05.dealloc.cta_group::1.sync.aligned.b32 %0, %1;" \
                 :: "r"(tmem), "r"((uint32_t)(n)))
#define TC_RELINQ() \
    asm volatile("tcgen05.relinquish_alloc_permit.cta_group::1.sync.aligned;")
#define TC_COMMIT(mbar) \
    asm volatile("tcgen05.commit.cta_group::1.mbarrier::arrive::one.shared::cluster.b64 [%0];" \
                 :: "r"((uint32_t)(mbar)) : "memory")
#define TC_WAIT_LD() asm volatile("tcgen05.wait::ld.sync.aligned;" ::: "memory")
#define TC_FENCE_BEFORE() asm volatile("tcgen05.fence::before_thread_sync;" ::: "memory")
#define TC_FENCE_AFTER()  asm volatile("tcgen05.fence::after_thread_sync;" ::: "memory")
#define TC_LD_X32(r, tmem)                                                        \
    asm volatile("tcgen05.ld.sync.aligned.32x32b.x32.b32 "                        \
        "{%0,%1,%2,%3,%4,%5,%6,%7,%8,%9,%10,%11,%12,%13,%14,%15,"                 \
        "%16,%17,%18,%19,%20,%21,%22,%23,%24,%25,%26,%27,%28,%29,%30,%31}, [%32];"\
        : "=r"((r)[0]),"=r"((r)[1]),"=r"((r)[2]),"=r"((r)[3]),                    \
          "=r"((r)[4]),"=r"((r)[5]),"=r"((r)[6]),"=r"((r)[7]),                    \
          "=r"((r)[8]),"=r"((r)[9]),"=r"((r)[10]),"=r"((r)[11]),                  \
          "=r"((r)[12]),"=r"((r)[13]),"=r"((r)[14]),"=r"((r)[15]),                \
          "=r"((r)[16]),"=r"((r)[17]),"=r"((r)[18]),"=r"((r)[19]),                \
          "=r"((r)[20]),"=r"((r)[21]),"=r"((r)[22]),"=r"((r)[23]),                \
          "=r"((r)[24]),"=r"((r)[25]),"=r"((r)[26]),"=r"((r)[27]),                \
          "=r"((r)[28]),"=r"((r)[29]),"=r"((r)[30]),"=r"((r)[31])                 \
        : "r"(tmem))

static constexpr uint64_t DESC_SW128 =
    (uint64_t(2) << 61) | (uint64_t(1) << 46) | (uint64_t(64) << 32) | (uint64_t(1) << 16);
__device__ __forceinline__ uint64_t make_desc(uint32_t addr) {
    return DESC_SW128 | ((uint64_t)(addr >> 4) & 0x3FFF);
}
// f16 idesc: c=F32(1<<4), atype=btype=F16(0), N<<17/8, M<<24/16
#define IDESC_F16_N256 0x8400010u
#define IDESC_F16_N128 0x8200010u
#define IDESC_F16_N64  0x8100010u
__device__ __forceinline__ void mma_f16_ss(uint32_t d, uint64_t ad, uint64_t bd,
                                           uint32_t idesc, uint32_t en) {
    uint32_t zero = 0;
    asm volatile("{ .reg .pred p; setp.ne.u32 p, %6, 0;"
                 " tcgen05.mma.cta_group::1.kind::f16 [%0], %1, %2, %3, "
                 "{%4, %4, %4, %4}, p; }"
                 :: "r"(d), "l"(ad), "l"(bd), "r"(idesc),
                    "r"(zero), "r"(zero), "r"(en) : "memory");
}
#endif  // HAS_TCGEN05

// ---------------- fused weight transpose: all 6 weights, one launch -----------
// out[C][R] = half(in[R][C]) per weight; flattened grid dispatch.
__global__ __launch_bounds__(256) void transpose_all(
    const float* __restrict__ wq, const float* __restrict__ wk,
    const float* __restrict__ wv, const float* __restrict__ wo,
    const float* __restrict__ w1, const float* __restrict__ w2,
    __half* __restrict__ wqkvT, __half* __restrict__ woT,
    __half* __restrict__ w1T, __half* __restrict__ w2T) {
    __shared__ float t[32][33];
    int id = blockIdx.x;
    const float* in;
    __half* out;
    int R, C, bx, by;
    if (id < 3072) {              // wq|wk|wv -> wqkvT sections (1024 blocks each)
        int w = id >> 10, r = id & 1023;
        in = (w == 0) ? wq : (w == 1) ? wk : wv;
        out = wqkvT + (size_t)w * DD * DD;
        R = DD; C = DD; bx = r & 31; by = r >> 5;
    } else if (id < 4096) {       // wo (1024 blocks)
        int r = id - 3072;
        in = wo; out = woT; R = DD; C = DD; bx = r & 31; by = r >> 5;
    } else if (id < 8192) {       // w1: R=DD, C=DFF (128 x 32 blocks)
        int r = id - 4096;
        in = w1; out = w1T; R = DD; C = DFF; bx = r & 127; by = r >> 7;
    } else {                      // w2: R=DFF, C=DD (32 x 128 blocks)
        int r = id - 8192;
        in = w2; out = w2T; R = DFF; C = DD; bx = r & 31; by = r >> 5;
    }
    int tx = threadIdx.x & 31, ty = threadIdx.x >> 5;
    int c0 = bx * 32, r0 = by * 32;
#pragma unroll
    for (int i = 0; i < 4; i++)
        t[ty + 8 * i][tx] = in[(size_t)(r0 + ty + 8 * i) * C + c0 + tx];
    __syncthreads();
#pragma unroll
    for (int i = 0; i < 4; i++)
        out[(size_t)(c0 + ty + 8 * i) * R + r0 + tx] = __float2half_rn(t[tx][ty + 8 * i]);
}

// ---------------- v transpose (from fused qkv, half) -> vT[b,h,dk,s] ----------
__global__ __launch_bounds__(256) void vt_kernel(const __half* __restrict__ vsec,
                                                 __half* __restrict__ vT) {
    __shared__ __half t[32][33];
    int tx = threadIdx.x & 31, ty = threadIdx.x >> 5;
    int bh = blockIdx.z;
    int b = bh >> 4, h = bh & 15;
    int s0 = blockIdx.x * 32, d0 = blockIdx.y * 32;
#pragma unroll
    for (int i = 0; i < 4; i++)
        t[ty + 8 * i][tx] =
            vsec[(size_t)(b * SS + s0 + ty + 8 * i) * QSTR + h * 64 + d0 + tx];
    __syncthreads();
#pragma unroll
    for (int i = 0; i < 4; i++)
        vT[((size_t)bh * DK + d0 + ty + 8 * i) * SS + s0 + tx] = t[tx][ty + 8 * i];
}

// ---------------- LayerNorm: 1 warp per row, fp32 in, fp16 out ----------------
__global__ __launch_bounds__(256) void ln_kernel(const float* __restrict__ x,
                                                 const float* __restrict__ g,
                                                 const float* __restrict__ b,
                                                 __half* __restrict__ out) {
    int w = threadIdx.x >> 5, lane = threadIdx.x & 31;
    int row = blockIdx.x * 8 + w;
    const float4* xr = reinterpret_cast<const float4*>(x + (size_t)row * DD);
    float4 v[8];
    float s = 0.f;
#pragma unroll
    for (int i = 0; i < 8; i++) {
        v[i] = xr[lane + 32 * i];
        s += v[i].x + v[i].y + v[i].z + v[i].w;
    }
#pragma unroll
    for (int o = 16; o > 0; o >>= 1) s += __shfl_xor_sync(~0u, s, o);
    float mu = s * (1.f / DD);
    float s2 = 0.f;
#pragma unroll
    for (int i = 0; i < 8; i++) {
        float dx = v[i].x - mu, dy = v[i].y - mu, dz = v[i].z - mu, dw = v[i].w - mu;
        s2 += dx * dx + dy * dy + dz * dz + dw * dw;
    }
#pragma unroll
    for (int o = 16; o > 0; o >>= 1) s2 += __shfl_xor_sync(~0u, s2, o);
    float rstd = rsqrtf(s2 * (1.f / DD) + EPS);
    const float4* gp = reinterpret_cast<const float4*>(g);
    const float4* bp = reinterpret_cast<const float4*>(b);
    uint2* op = reinterpret_cast<uint2*>(out + (size_t)row * DD);
#pragma unroll
    for (int i = 0; i < 8; i++) {
        float4 gg = gp[lane + 32 * i], bb = bp[lane + 32 * i];
        __half2 lo = __floats2half2_rn((v[i].x - mu) * rstd * gg.x + bb.x,
                                       (v[i].y - mu) * rstd * gg.y + bb.y);
        __half2 hi = __floats2half2_rn((v[i].z - mu) * rstd * gg.z + bb.z,
                                       (v[i].w - mu) * rstd * gg.w + bb.w);
        uint2 u;
        u.x = *reinterpret_cast<uint32_t*>(&lo);
        u.y = *reinterpret_cast<uint32_t*>(&hi);
        op[lane + 32 * i] = u;
    }
}

// ---------------- GEMM: C[M,N] = A[M,K] @ BT[N,K]^T (fp16, R15 proven) --------
#define TN 256
#define NST 2
#define STAGE (16384 + 32768)
#define GT_SMEM (1024 + NST * STAGE)   // 99328

template <bool BIAS, bool RELU, bool RES, bool HALFOUT, bool QKVSCALE>
__global__ __launch_bounds__(256)
void gemm_tc(const __half* __restrict__ A, const __half* __restrict__ BT,
             const float* __restrict__ bias, const float* __restrict__ res,
             void* __restrict__ Cv, int N, int K) {
#if HAS_TCGEN05
    extern __shared__ char smem[];
    uint32_t sb = smem_u32(smem);
    int tid = threadIdx.x;
    int wid = tid >> 5, lid = tid & 31;
    int bm0 = blockIdx.y * 128, bn0 = blockIdx.x * TN;

    if (wid == 0) {
        TC_ALLOC(sb, TN);
        TC_RELINQ();
    }
    if (tid == 0) { MBAR_INIT(sb + 8, 1); MBAR_INIT(sb + 16, 1); }
    __syncthreads();
    uint32_t tmem;
    asm volatile("ld.shared.b32 %0, [%1];" : "=r"(tmem) : "r"(sb));

    const int nc = K >> 6;   // K-chunks of 64 halves (128 bytes)

    auto issue_stage = [&](int t) {
        int s = t % NST;
        uint32_t ab = sb + 1024 + s * STAGE;
        const __half* Ag = A + (size_t)bm0 * K + t * 64;
        const __half* Bg = BT + (size_t)bn0 * K + t * 64;
#pragma unroll
        for (int i = 0; i < 4; i++) {           // A: 128 rows x 8 segs
            int idx = tid + 256 * i;
            int r = idx >> 3, f = idx & 7;
            uint32_t off = (uint32_t)(r * 128 + f * 16);
            off ^= (off >> 3) & 0x70;
            CP16(ab + off, Ag + (size_t)r * K + f * 8);
        }
#pragma unroll
        for (int i = 0; i < 8; i++) {           // B: 256 rows x 8 segs
            int idx = tid + 256 * i;
            int r = idx >> 3, f = idx & 7;
            uint32_t off = (uint32_t)(r * 128 + f * 16);
            off ^= (off >> 3) & 0x70;
            CP16(ab + 16384 + off, Bg + (size_t)r * K + f * 8);
        }
        CP_COMMIT();
    };

    issue_stage(0);
    issue_stage(1);

    for (int t = 0; t < nc; t++) {
        if (t < nc - NST) { CP_WAIT1(); } else { CP_WAIT0(); }
        FENCE_ASYNC();
        __syncthreads();
        if (wid == 0 && elect_one()) {
            uint32_t base = sb + 1024 + (t % NST) * STAGE;
            uint64_t ad = make_desc(base);
            uint64_t bd = make_desc(base + 16384);
#pragma unroll
            for (int k = 0; k < 4; k++)   // K=16 per MMA, 4 per chunk
                mma_f16_ss(tmem, ad + k * 2, bd + k * 2, IDESC_F16_N256,
                           (t > 0 || k > 0) ? 1u : 0u);
            TC_COMMIT(sb + 8 + 8 * (t % NST));
        }
        if (t + NST < nc) {
            MBAR_WAIT(sb + 8 + 8 * (t % NST), (t / NST) & 1);
            issue_stage(t + NST);
        }
    }
    for (int tt = nc - NST; tt < nc; tt++)
        MBAR_WAIT(sb + 8 + 8 * (tt % NST), (tt / NST) & 1);
    TC_FENCE_AFTER();
    __syncthreads();

    // epilogue: warps 0-3 read TMEM, transpose via smem, store coalesced
    float cm = 1.f;
    if (QKVSCALE) cm = (bn0 < DD) ? 0.125f : 1.f;
    if (tid < 128) {
        float* tw = reinterpret_cast<float*>(smem + 1024) + wid * (32 * 33 + 8);
#pragma unroll
        for (int cb = 0; cb < TN; cb += 32) {
            uint32_t regs[32];
            TC_LD_X32(regs, tmem + cb);
            TC_WAIT_LD();
#pragma unroll
            for (int j = 0; j < 32; j++) tw[lid * 33 + j] = __uint_as_float(regs[j]);
            __syncwarp();
            float bv = BIAS ? bias[bn0 + cb + lid] : 0.f;
#pragma unroll 4
            for (int r = 0; r < 32; r++) {
                int row = bm0 + wid * 32 + r;
                int col = bn0 + cb + lid;
                float v = tw[r * 33 + lid];
                if (QKVSCALE) v *= cm;
                if (BIAS) v += bv;
                if (RELU) v = fmaxf(v, 0.f);
                if (HALFOUT) {
                    reinterpret_cast<__half*>(Cv)[(size_t)row * N + col] =
                        __float2half_rn(v);
                } else {
                    if (RES) v += res[(size_t)row * N + col];
                    reinterpret_cast<float*>(Cv)[(size_t)row * N + col] = v;
                }
            }
            __syncwarp();
        }
    }
    TC_FENCE_BEFORE();
    __syncthreads();
    if (wid == 0) TC_DEALLOC(tmem, TN);
#else
    // SIMT fallback (plain sm_103 pass; not expected to be selected)
    extern __shared__ char smem[];
    float* As = reinterpret_cast<float*>(smem);          // [16][128]
    float* Bs = As + 16 * 128;
    int tid = threadIdx.x;
    int bm0 = blockIdx.y * 128;
    int tx = tid & 15, ty = tid >> 4;
    for (int nh = 0; nh < TN / 128; nh++) {
        int bn0 = blockIdx.x * TN + nh * 128;
        float cm = 1.f;
        if (QKVSCALE) cm = (bn0 < DD) ? 0.125f : 1.f;
        float acc[8][8];
#pragma unroll
        for (int i = 0; i < 8; i++)
#pragma unroll
            for (int j = 0; j < 8; j++) acc[i][j] = 0.f;
        for (int kt = 0; kt < K; kt += 16) {
            __syncthreads();
            for (int idx = tid; idx < 128 * 16; idx += 256) {
                int r = idx >> 4, c = idx & 15;
                As[c * 128 + r] = __half2float(A[(size_t)(bm0 + r) * K + kt + c]);
                Bs[c * 128 + r] = __half2float(BT[(size_t)(bn0 + r) * K + kt + c]);
            }
            __syncthreads();
#pragma unroll
            for (int k = 0; k < 16; k++) {
                float a[8], bb[8];
#pragma unroll
                for (int i = 0; i < 4; i++) {
                    a[i] = As[k * 128 + ty * 4 + i];
                    a[i + 4] = As[k * 128 + 64 + ty * 4 + i];
                    bb[i] = Bs[k * 128 + tx * 4 + i];
                    bb[i + 4] = Bs[k * 128 + 64 + tx * 4 + i];
                }
#pragma unroll
                for (int i = 0; i < 8; i++)
#pragma unroll
                    for (int j = 0; j < 8; j++) acc[i][j] = fmaf(a[i], bb[j], acc[i][j]);
            }
        }
#pragma unroll
        for (int i = 0; i < 8; i++) {
            int row = bm0 + ((i < 4) ? (ty * 4 + i) : (64 + ty * 4 + i - 4));
#pragma unroll
            for (int j = 0; j < 8; j++) {
                int col = bn0 + ((j < 4) ? (tx * 4 + j) : (64 + tx * 4 + j - 4));
                float v = acc[i][j];
                if (QKVSCALE) v *= cm;
                if (BIAS) v += bias[col];
                if (RELU) v = fmaxf(v, 0.f);
                if (HALFOUT) {
                    reinterpret_cast<__half*>(Cv)[(size_t)row * N + col] =
                        __float2half_rn(v);
                } else {
                    if (RES) v += res[(size_t)row * N + col];
                    reinterpret_cast<float*>(Cv)[(size_t)row * N + col] = v;
                }
            }
        }
        __syncthreads();
    }
#endif
}

// ---------------- tcgen05 attention: 2 CTAs/SM config -------------------------
// grid (S/128, H, B), 256 threads. TMEM: S@0 (128), O@128 (64); alloc 256.
// smem: misc@0 (rs@1024), Q@2048 (16KB), K@18432 (16KB), V@34816 (16KB),
// P@51200 (32KB); epilogue float staging (ob) reuses K+V region @18432.
// Total 86016 -> 2 CTAs/SM; cross-CTA interleave hides the serial chain.
#define AT_Q 2048u
#define AT_K 18432u
#define AT_V 34816u
#define AT_P 51200u
#define AT_OB 18432u
#define ATTN_TC_SMEM 86016

__global__ __launch_bounds__(256)
void attn_tc(const __half* __restrict__ Q, const __half* __restrict__ K,
             const __half* __restrict__ vT, __half* __restrict__ O) {
#if HAS_TCGEN05
    extern __shared__ char smem[];
    uint32_t sb = smem_u32(smem);
    int tid = threadIdx.x;
    int wid = tid >> 5, lane = tid & 31;
    int b = blockIdx.z, h = blockIdx.y;
    int q0 = blockIdx.x * 128;

    if (wid == 0) {
        TC_ALLOC(sb, 256);
        TC_RELINQ();
    }
    if (tid == 0) { MBAR_INIT(sb + 8, 1); MBAR_INIT(sb + 16, 1); }
    __syncthreads();
    uint32_t tmem;
    asm volatile("ld.shared.b32 %0, [%1];" : "=r"(tmem) : "r"(sb));
    uint32_t tmem_O = tmem + 128;

    auto issue_kv = [&](int t) {
        const __half* Kp = K + (size_t)(b * SS + t * 128) * QSTR + h * 64;
#pragma unroll
        for (int i = 0; i < 4; i++) {           // K: 128 rows x 8 segs (16KB)
            int idx = tid + 256 * i;
            int r = idx >> 3, f = idx & 7;
            uint32_t byte = (uint32_t)(r * 128 + f * 16);
            byte ^= (byte >> 3) & 0x70;
            CP16(sb + AT_K + byte, Kp + (size_t)r * QSTR + f * 8);
        }
        const __half* Vp = vT + ((size_t)(b * HH + h) * DK) * SS + t * 128;
#pragma unroll
        for (int i = 0; i < 4; i++) {           // V: 64 rows x 16 segs (16KB)
            int idx = tid + 256 * i;
            int d = idx >> 4, f = idx & 15;
            uint32_t byte = (uint32_t)(((d >> 3) + (f >> 3) * 8) * 1024 +
                                       (d & 7) * 128 + (f & 7) * 16);
            byte ^= (byte >> 3) & 0x70;
            CP16(sb + AT_V + byte, Vp + (size_t)d * SS + f * 8);
        }
        CP_COMMIT();
    };

    uint64_t descQ = make_desc(sb + AT_Q);

    // prologue: Q + kv(0) in one commit group
    {
        const __half* Qp = Q + (size_t)(b * SS + q0) * QSTR + h * 64;
#pragma unroll
        for (int i = 0; i < 4; i++) {
            int idx = tid + 256 * i;
            int r = idx >> 3, f = idx & 7;
            uint32_t byte = (uint32_t)(r * 128 + f * 16);
            byte ^= (byte >> 3) & 0x70;
            CP16(sb + AT_Q + byte, Qp + (size_t)r * QSTR + f * 8);
        }
        issue_kv(0);
    }

    float rsum = 0.f;
    const int sp = wid & 3;
    const int srow = sp * 32 + lane;
    const int colbase = (wid >> 2) * 64;

    for (int t = 0; t < 16; t++) {
        CP_WAIT0();       // kv(t) resident
        FENCE_ASYNC();
        __syncthreads();

        if (wid == 0 && elect_one()) {
            // S(t) = Q @ K(t)^T, K=64: 4 dispatches
            uint64_t descK = make_desc(sb + AT_K);
#pragma unroll
            for (int k = 0; k < 4; k++)
                mma_f16_ss(tmem, descQ + k * 2, descK + k * 2,
                           IDESC_F16_N128, k > 0 ? 1u : 0u);
            TC_COMMIT(sb + 8);
        }
        MBAR_WAIT(sb + 8, t & 1);
        TC_FENCE_AFTER();

        // softmax(t): warp w handles cols [colbase, colbase+64); P stored fp16
#pragma unroll
        for (int cb2 = 0; cb2 < 64; cb2 += 32) {
            uint32_t regs[32];
            TC_LD_X32(regs, tmem + colbase + cb2);
            TC_WAIT_LD();
            float e[32];
#pragma unroll
            for (int j = 0; j < 32; j++) {
                e[j] = __expf(__uint_as_float(regs[j]));
                rsum += e[j];
            }
#pragma unroll
            for (int j0 = 0; j0 < 32; j0 += 8) {
                uint4 u;
                __half2 h0 = __floats2half2_rn(e[j0 + 0], e[j0 + 1]);
                __half2 h1 = __floats2half2_rn(e[j0 + 2], e[j0 + 3]);
                __half2 h2 = __floats2half2_rn(e[j0 + 4], e[j0 + 5]);
                __half2 h3 = __floats2half2_rn(e[j0 + 6], e[j0 + 7]);
                u.x = *reinterpret_cast<uint32_t*>(&h0);
                u.y = *reinterpret_cast<uint32_t*>(&h1);
                u.z = *reinterpret_cast<uint32_t*>(&h2);
                u.w = *reinterpret_cast<uint32_t*>(&h3);
                int c = colbase + cb2 + j0;
                int cbyte = 2 * c;
                uint32_t byte = (uint32_t)(((srow >> 3) + (cbyte >> 7) * 16) * 1024 +
                                           (srow & 7) * 128 + (cbyte & 127));
                byte ^= (byte >> 3) & 0x70;
                *reinterpret_cast<uint4*>(smem + AT_P + byte) = u;
            }
        }
        FENCE_ASYNC();
        __syncthreads();  // P ready

        if (wid == 0 && elect_one()) {
            // PV(t): O += P @ V(t)^T, K=128: 8 dispatches
            uint64_t descP = make_desc(sb + AT_P);
            uint64_t descV = make_desc(sb + AT_V);
#pragma unroll
            for (int k = 0; k < 8; k++)
                mma_f16_ss(tmem_O,
                           descP + (k >> 2) * 1024 + (k & 3) * 2,
                           descV + (k >> 2) * 512 + (k & 3) * 2,
                           IDESC_F16_N64, (t > 0 || k > 0) ? 1u : 0u);
            TC_COMMIT(sb + 16);
        }
        MBAR_WAIT(sb + 16, t & 1);  // PV(t) done: K/V/P reusable
        if (t + 1 < 16) issue_kv(t + 1);
    }
    TC_FENCE_AFTER();

    // combine per-warp rsum partials (warps w and w+4 share rows)
    float* rs = reinterpret_cast<float*>(smem + 1024);
    rs[wid * 32 + lane] = rsum;
    __syncthreads();

    // epilogue: normalize O, stage as float over dead K/V region, store fp16
    float* ob = reinterpret_cast<float*>(smem + AT_OB);
    if (wid < 4) {
        float inv = 1.f / (rs[wid * 32 + lane] + rs[(wid + 4) * 32 + lane]);
        uint32_t r0[32], r1[32];
        TC_LD_X32(r0, tmem_O);
        TC_LD_X32(r1, tmem_O + 32);
        TC_WAIT_LD();
#pragma unroll
        for (int j = 0; j < 32; j++) {
            ob[srow * 68 + j] = __uint_as_float(r0[j]) * inv;
            ob[srow * 68 + 32 + j] = __uint_as_float(r1[j]) * inv;
        }
    }
    TC_FENCE_BEFORE();
    __syncthreads();
#pragma unroll
    for (int p = 0; p < 8; p++) {
        int slot = tid + 256 * p;
        int r = slot >> 4, f = slot & 15;
        __half2 lo = __floats2half2_rn(ob[r * 68 + f * 4 + 0], ob[r * 68 + f * 4 + 1]);
        __half2 hi = __floats2half2_rn(ob[r * 68 + f * 4 + 2], ob[r * 68 + f * 4 + 3]);
        uint2 u;
        u.x = *reinterpret_cast<uint32_t*>(&lo);
        u.y = *reinterpret_cast<uint32_t*>(&hi);
        *reinterpret_cast<uint2*>(O + (size_t)(b * SS + q0 + r) * DD + h * 64 + f * 4) = u;
    }
    __syncthreads();
    if (wid == 0) TC_DEALLOC(tmem, 256);
#else
    // naive SIMT fallback (q pre-scaled by 1/8; qkv strided, half)
    int tid = threadIdx.x;
    int b = blockIdx.z, h = blockIdx.y;
    int q0 = blockIdx.x * 128;
    int r = tid >> 1, dh = (tid & 1) * 32;
    const __half* qp = Q + (size_t)(b * SS + q0 + r) * QSTR + h * 64;
    float acc[32];
#pragma unroll
    for (int j = 0; j < 32; j++) acc[j] = 0.f;
    float l = 0.f;
    for (int kv = 0; kv < SS; kv++) {
        const __half* kp = K + (size_t)(b * SS + kv) * QSTR + h * 64;
        float s = 0.f;
        for (int d = 0; d < 64; d++) s += __half2float(qp[d]) * __half2float(kp[d]);
        float e = __expf(s);
        l += e;
        const __half* vp = vT + ((size_t)(b * HH + h) * DK + dh) * SS + kv;
        for (int j = 0; j < 32; j++) acc[j] += e * __half2float(vp[(size_t)j * SS]);
    }
    float inv = 1.f / l;
    __half* op = O + (size_t)(b * SS + q0 + r) * DD + h * 64 + dh;
    for (int j = 0; j < 32; j++) op[j] = __float2half_rn(acc[j] * inv);
#endif
}

// ---------------- launch -------------------------------------------------------
extern "C" void kernel_launch(void* const* d_in, const int* in_sizes, int n_in,
                              void* d_out, int out_size) {
    const float* x   = (const float*)d_in[0];
    const float* wq  = (const float*)d_in[1];
    const float* wk  = (const float*)d_in[2];
    const float* wv  = (const float*)d_in[3];
    const float* wo  = (const float*)d_in[4];
    const float* w1  = (const float*)d_in[5];
    const float* b1  = (const float*)d_in[6];
    const float* w2  = (const float*)d_in[7];
    const float* b2  = (const float*)d_in[8];
    const float* g1  = (const float*)d_in[9];
    const float* be1 = (const float*)d_in[10];
    const float* g2  = (const float*)d_in[11];
    const float* be2 = (const float*)d_in[12];
    float* out = (float*)d_out;

    __half *h, *qkv, *attn, *ffn, *vT, *wqkvT, *woT, *w1T, *w2T;
    float *x1;
    cudaGetSymbolAddress((void**)&h, g_h);
    cudaGetSymbolAddress((void**)&qkv, g_qkv);
    cudaGetSymbolAddress((void**)&attn, g_attn);
    cudaGetSymbolAddress((void**)&x1, g_x1);
    cudaGetSymbolAddress((void**)&ffn, g_ffn);
    cudaGetSymbolAddress((void**)&vT, g_vT);
    cudaGetSymbolAddress((void**)&wqkvT, g_wqkvT);
    cudaGetSymbolAddress((void**)&woT, g_woT);
    cudaGetSymbolAddress((void**)&w1T, g_w1T);
    cudaGetSymbolAddress((void**)&w2T, g_w2T);

    static bool attr_done = false;
    if (!attr_done) {
        cudaFuncSetAttribute(attn_tc,
                             cudaFuncAttributeMaxDynamicSharedMemorySize, ATTN_TC_SMEM);
        cudaFuncSetAttribute(gemm_tc<false, false, false, true, true>,
                             cudaFuncAttributeMaxDynamicSharedMemorySize, GT_SMEM);
        cudaFuncSetAttribute(gemm_tc<false, false, true, false, false>,
                             cudaFuncAttributeMaxDynamicSharedMemorySize, GT_SMEM);
        cudaFuncSetAttribute(gemm_tc<true, true, false, true, false>,
                             cudaFuncAttributeMaxDynamicSharedMemorySize, GT_SMEM);
        cudaFuncSetAttribute(gemm_tc<true, false, true, false, false>,
                             cudaFuncAttributeMaxDynamicSharedMemorySize, GT_SMEM);
        attr_done = true;
    }

    // all weight transposes in one launch
    transpose_all<<<12288, 256>>>(wq, wk, wv, wo, w1, w2, wqkvT, woT, w1T, w2T);

    dim3 gQKV(3 * DD / TN, NT / 128);   // (12, 64)
    dim3 gWo(DD / TN, NT / 128);        // (4, 64)
    dim3 gF1(DFF / TN, NT / 128);       // (16, 64)
    dim3 gF2(DD / TN, NT / 128);        // (4, 64)

    ln_kernel<<<NT / 8, 256>>>(x, g1, be1, h);
    gemm_tc<false, false, false, true, true><<<gQKV, 256, GT_SMEM>>>(
        h, wqkvT, nullptr, nullptr, qkv, 3 * DD, DD);
    vt_kernel<<<dim3(SS / 32, DK / 32, BB * HH), 256>>>(qkv + 2 * DD, vT);
    attn_tc<<<dim3(SS / 128, HH, BB), 256, ATTN_TC_SMEM>>>(qkv, qkv + DD, vT, attn);
    gemm_tc<false, false, true, false, false><<<gWo, 256, GT_SMEM>>>(
        attn, woT, nullptr, x, x1, DD, DD);
    ln_kernel<<<NT / 8, 256>>>(x1, g2, be2, h);
    gemm_tc<true, true, false, true, false><<<gF1, 256, GT_SMEM>>>(
        h, w1T, b1, nullptr, ffn, DFF, DD);
    gemm_tc<true, false, true, false, false><<<gF2, 256, GT_SMEM>>>(
        ffn, w2T, b2, x1, out, DD, DFF);
}